// round 5
// baseline (speedup 1.0000x reference)
#include <cuda_runtime.h>
#include <math.h>

#define BATCH 8
#define CW    64
#define H0    256
#define W0    256
#define HP    264
#define WP    264
#define MW    32      // kept kx modes
#define MH    64      // kept ky modes (32 top + 32 bottom)
#define NL    4
#define HW    (HP*WP)            // 69696
#define NPIX  (BATCH*CW*HW)      // 35684352

typedef unsigned long long u64;

// ---------------- scratch (device globals; no allocation allowed) ----------
__device__ __align__(128) float  g_h[2][NPIX];              // 2 x 142.7 MB
__device__ __align__(128) float2 g_x1[BATCH*CW*HP*MW];      // 34.6 MB
__device__ __align__(128) float2 g_x2[BATCH*CW*MH*MW];      // 8.4 MB
__device__ __align__(128) float2 g_y2[BATCH*CW*MH*MW];      // 8.4 MB
__device__ __align__(128) float2 g_y1[BATCH*CW*HP*MW];      // 34.6 MB
__device__ __align__(128) float4 g_fw4[WP*MW];              // [w][kx] (c,c,-s,-s)
__device__ __align__(128) float4 g_fh4[HP*MH];              // [h][j]  (c,c,s,-s)
__device__ __align__(128) float4 g_gh4a[HP*MH];             // [h][j]  (c,c,-s,-s)
__device__ __align__(128) float4 g_gh4b[HP*MH];             // [h][j]  (c,c,s,s)
__device__ __align__(128) float  g_aw[2*MW*WP];             // c2r inverse-W [kk][w]

__device__ __forceinline__ float gelu_f(float v) {
    return 0.5f * v * (1.0f + erff(v * 0.70710678118654752f));
}

// ---------------- f32x2 helpers -------------------------------------------
__device__ __forceinline__ u64 pk2(float lo, float hi) {
    u64 r;
    asm("mov.b64 %0, {%1, %2};" : "=l"(r)
        : "r"(__float_as_uint(lo)), "r"(__float_as_uint(hi)));
    return r;
}
__device__ __forceinline__ u64 bcast2(float v) { return pk2(v, v); }
__device__ __forceinline__ void fma2(u64& d, u64 a, u64 b) {
    asm("fma.rn.f32x2 %0, %1, %2, %0;" : "+l"(d) : "l"(a), "l"(b));
}
__device__ __forceinline__ float2 up2(u64 v) {
    unsigned int a, b;
    asm("mov.b64 {%0, %1}, %2;" : "=r"(a), "=r"(b) : "l"(v));
    return make_float2(__uint_as_float(a), __uint_as_float(b));
}

// ---------------- twiddle/matrix init (double-precision trig) --------------
__global__ void k_init() {
    int i = blockIdx.x * blockDim.x + threadIdx.x;
    if (i >= HP * MH) return;   // 16896
    const double TWO_PI = 6.283185307179586476925286766559;
    {   // g_fh4 / g_gh4a / g_gh4b : [h][j]
        int h = i >> 6, j = i & 63;
        int ky = (j < 32) ? j : (j + (HP - MH));
        long m = ((long)h * (long)ky) % HP;
        double ang = TWO_PI * (double)m / (double)HP;
        double s, c; sincos(ang, &s, &c);
        float cf = (float)c, sf = (float)s;
        g_fh4[i]  = make_float4(cf, cf,  sf, -sf);
        g_gh4a[i] = make_float4(cf, cf, -sf, -sf);
        g_gh4b[i] = make_float4(cf, cf,  sf,  sf);
    }
    if (i < WP * MW) {  // g_fw4 : [w][kx] (c,c,-s,-s)
        int w = i >> 5, k = i & 31;
        long m = ((long)w * (long)k) % WP;
        double ang = TWO_PI * (double)m / (double)WP;
        double s, c; sincos(ang, &s, &c);
        g_fw4[i] = make_float4((float)c, (float)c, (float)(-s), (float)(-s));
    }
    {   // g_aw : [kk][w]
        int kk = i / WP, w = i - kk * WP;
        int k = kk >> 1;
        double sc = ((k == 0) ? 1.0 : 2.0) / ((double)HP * (double)WP);
        long m = ((long)k * (long)w) % WP;
        double ang = TWO_PI * (double)m / (double)WP;
        double s, c; sincos(ang, &s, &c);
        g_aw[i] = (float)((kk & 1) ? (-sc * s) : (sc * c));
    }
}

__global__ void k_zero() {
    float4* p = (float4*)g_h[0];
    size_t n4 = (size_t)NPIX / 4;
    for (size_t i = (size_t)blockIdx.x * blockDim.x + threadIdx.x; i < n4;
         i += (size_t)gridDim.x * blockDim.x)
        p[i] = make_float4(0.f, 0.f, 0.f, 0.f);
}

// ---------------- lift: [x, gx, gy] -> gelu(W1.) -> W2. -------------------
__global__ void k_lift(const float* __restrict__ x,
                       const float* __restrict__ w1, const float* __restrict__ b1,
                       const float* __restrict__ w2, const float* __restrict__ b2) {
    __shared__ float sw1[160], sb1[32], sw2[2048], sb2[64];
    int t = threadIdx.x;
    if (t < 160) sw1[t] = w1[t];
    if (t < 32)  sb1[t] = b1[t];
    for (int i = t; i < 2048; i += 256) sw2[i] = w2[i];
    if (t < 64)  sb2[t] = b2[t];
    __syncthreads();
    int b = blockIdx.x >> 8, h = blockIdx.x & 255, w = t;
    float in5[5];
#pragma unroll
    for (int c = 0; c < 3; ++c)
        in5[c] = x[(((size_t)b * 3 + c) * H0 + h) * W0 + w];
    in5[3] = (float)h * (1.0f / 255.0f);
    in5[4] = (float)w * (1.0f / 255.0f);
    float mid[32];
#pragma unroll
    for (int o = 0; o < 32; ++o) {
        float s = sb1[o];
#pragma unroll
        for (int i = 0; i < 5; ++i) s = fmaf(sw1[o * 5 + i], in5[i], s);
        mid[o] = gelu_f(s);
    }
    float* hb = g_h[0];
#pragma unroll 4
    for (int o = 0; o < 64; ++o) {
        float s = sb2[o];
#pragma unroll
        for (int i = 0; i < 32; ++i) s = fmaf(sw2[o * 32 + i], mid[i], s);
        hb[(((size_t)b * CW + o) * HP + h) * WP + w] = s;
    }
}

// ---------------- K1: partial rDFT along W  (h -> x1), f32x2 ---------------
// 64-row tile stored transposed sAT[w][66]; acc packed over row pairs.
__global__ __launch_bounds__(256) void k1_wdft(int cur) {
    extern __shared__ float sAT[];                       // [264][66] 69696 B
    const float* hb = g_h[cur] + (size_t)blockIdx.x * 64 * WP;
    for (int idx = threadIdx.x; idx < 64 * WP; idx += 256) {
        int r = idx / WP, w = idx - r * WP;
        sAT[w * 66 + r] = hb[idx];
    }
    __syncthreads();
    int kx = threadIdx.x & 31, rb = threadIdx.x >> 5;    // warp: rows rb*8..rb*8+7
    u64 are[4], aim[4];
#pragma unroll
    for (int p = 0; p < 4; ++p) { are[p] = 0ull; aim[p] = 0ull; }
    const longlong2* tw = reinterpret_cast<const longlong2*>(g_fw4);
#pragma unroll 2
    for (int w = 0; w < WP; ++w) {
        longlong2 T = __ldg(&tw[w * 32 + kx]);           // (c,c | -s,-s)
        u64 cc = (u64)T.x, ss = (u64)T.y;
        const float* row = &sAT[w * 66 + rb * 8];
#pragma unroll
        for (int p = 0; p < 4; ++p) {
            u64 d = *reinterpret_cast<const u64*>(row + 2 * p);  // rows 2p,2p+1
            fma2(are[p], d, cc);
            fma2(aim[p], d, ss);
        }
    }
    size_t row0 = (size_t)blockIdx.x * 64 + rb * 8;
#pragma unroll
    for (int p = 0; p < 4; ++p) {
        float2 re = up2(are[p]), im = up2(aim[p]);
        g_x1[(row0 + 2 * p    ) * MW + kx] = make_float2(re.x, im.x);
        g_x1[(row0 + 2 * p + 1) * MW + kx] = make_float2(re.y, im.y);
    }
}

// ---------------- K2: partial DFT along H  (x1 -> x2), f32x2 ---------------
__global__ void k2_hdft() {
    extern __shared__ float s_raw[];
    float2* sX = reinterpret_cast<float2*>(s_raw);       // [h][kx] 264x32
    int bc = blockIdx.x;
    const float4* src = reinterpret_cast<const float4*>(g_x1 + (size_t)bc * HP * MW);
    float4* dst = reinterpret_cast<float4*>(sX);
    for (int i = threadIdx.x; i < (HP * MW) / 2; i += 256) dst[i] = src[i];
    __syncthreads();
    int kx = threadIdx.x & 31, jg = threadIdx.x >> 5;    // jg: 0..7, 8 j's each
    u64 acc[8];
#pragma unroll
    for (int q = 0; q < 8; ++q) acc[q] = 0ull;
    const longlong2* tw = reinterpret_cast<const longlong2*>(g_fh4);
#pragma unroll 2
    for (int h = 0; h < HP; ++h) {
        u64 xvp = *reinterpret_cast<const u64*>(&sX[h * MW + kx]);
        float2 xv = up2(xvp);
        u64 xvs = pk2(xv.y, xv.x);
        const longlong2* row = &tw[h * MH + jg * 8];
#pragma unroll
        for (int q = 0; q < 8; ++q) {
            longlong2 T = __ldg(&row[q]);                // (c,c | s,-s)
            fma2(acc[q], (u64)T.x, xvp);                 // (c*x, c*y)
            fma2(acc[q], (u64)T.y, xvs);                 // (s*y, -s*x)
        }
    }
#pragma unroll
    for (int q = 0; q < 8; ++q)
        *reinterpret_cast<u64*>(&g_x2[((size_t)bc * MH + jg * 8 + q) * MW + kx]) = acc[q];
}

// ---------------- K3: per-mode channel mixing (x2 -> y2) -------------------
__global__ __launch_bounds__(256) void k3_mix(const float* __restrict__ spw1,
                                              const float* __restrict__ spw2, int l) {
    __shared__ float2 sX[2 * 64 * 32];                   // [b2][i][kx] 32 KB
    int jj = blockIdx.x >> 2, bp = blockIdx.x & 3;
    int b0 = bp * 2;
    int t = threadIdx.x, kx = t & 31, sub = t >> 5;      // sub 0..7 -> o = sub*8+q
    for (int idx = t; idx < 4096; idx += 256) {
        int bi = idx >> 11, rest = idx & 2047;
        int i = rest >> 5, kxl = rest & 31;
        sX[idx] = g_x2[(((size_t)(b0 + bi) * CW + i) * MH + jj) * MW + kxl];
    }
    __syncthreads();
    const float2* wp; int jx;
    if (jj < 32) { wp = (const float2*)spw1; jx = jj; }
    else         { wp = (const float2*)spw2; jx = jj - 32; }
    size_t wbase = (size_t)l * 4194304 + (size_t)jx * 32 + kx;
    float2 a0[8], a1[8];
#pragma unroll
    for (int q = 0; q < 8; ++q) { a0[q] = make_float2(0.f, 0.f); a1[q] = make_float2(0.f, 0.f); }
#pragma unroll 2
    for (int i = 0; i < 64; ++i) {
        float2 x0 = sX[i * 32 + kx];
        float2 x1 = sX[2048 + i * 32 + kx];
        size_t row = wbase + (size_t)(i * 64 + sub * 8) * 1024;
#pragma unroll
        for (int q = 0; q < 8; ++q) {
            float2 c = __ldg(&wp[row + (size_t)q * 1024]);
            a0[q].x = fmaf(x0.x, c.x, a0[q].x); a0[q].x = fmaf(-x0.y, c.y, a0[q].x);
            a0[q].y = fmaf(x0.x, c.y, a0[q].y); a0[q].y = fmaf( x0.y, c.x, a0[q].y);
            a1[q].x = fmaf(x1.x, c.x, a1[q].x); a1[q].x = fmaf(-x1.y, c.y, a1[q].x);
            a1[q].y = fmaf(x1.x, c.y, a1[q].y); a1[q].y = fmaf( x1.y, c.x, a1[q].y);
        }
    }
#pragma unroll
    for (int q = 0; q < 8; ++q) {
        int o = sub * 8 + q;
        g_y2[(((size_t)b0       * CW + o) * MH + jj) * MW + kx] = a0[q];
        g_y2[(((size_t)(b0 + 1) * CW + o) * MH + jj) * MW + kx] = a1[q];
    }
}

// ---------------- K4: inverse DFT along H (y2 -> y1), f32x2 ----------------
// sY split into re/im planes; acc packed over kx-pairs.
__global__ void k4_invh() {
    __shared__ float sYre[MH * MW];                      // 8 KB
    __shared__ float sYim[MH * MW];                      // 8 KB
    int bo = blockIdx.x;
    const float2* src = g_y2 + (size_t)bo * MH * MW;
    for (int i = threadIdx.x; i < MH * MW; i += 256) {
        float2 v = src[i];
        sYre[i] = v.x; sYim[i] = v.y;
    }
    __syncthreads();
    int kxp = threadIdx.x & 15, hg = threadIdx.x >> 4;   // kx pair, 16 h-groups
    int kx0 = kxp * 2;
    const longlong2* ta = reinterpret_cast<const longlong2*>(g_gh4a);
    const longlong2* tb = reinterpret_cast<const longlong2*>(g_gh4b);
    for (int k = 0; k < 17; ++k) {
        int h = k * 16 + hg;
        if (h < HP) {
            u64 accre = 0ull, accim = 0ull;
            const longlong2* rowa = &ta[h * MH];
            const longlong2* rowb = &tb[h * MH];
#pragma unroll 8
            for (int j = 0; j < 64; ++j) {
                longlong2 TA = __ldg(&rowa[j]);          // (c,c | -s,-s)
                longlong2 TB = __ldg(&rowb[j]);          // (c,c |  s, s)
                u64 yre = *reinterpret_cast<const u64*>(&sYre[j * MW + kx0]);
                u64 yim = *reinterpret_cast<const u64*>(&sYim[j * MW + kx0]);
                fma2(accre, (u64)TA.x, yre);             // + c*yre
                fma2(accre, (u64)TA.y, yim);             // - s*yim
                fma2(accim, (u64)TB.x, yim);             // + c*yim
                fma2(accim, (u64)TB.y, yre);             // + s*yre
            }
            float2 r = up2(accre), im = up2(accim);
            float4 outv = make_float4(r.x, im.x, r.y, im.y);
            *reinterpret_cast<float4*>(&g_y1[((size_t)bo * HP + h) * MW + kx0]) = outv;
        }
    }
}

// ---------------- K5: conv1x1 + inverse-W(c2r) + bias + gelu, f32x2 --------
// block = (b, h); acc packed over o-pairs.
__global__ __launch_bounds__(264, 2)
void k5_combine(int cur, const float* __restrict__ cw,
                const float* __restrict__ cb, int l,
                float* __restrict__ out) {
    extern __shared__ float s_raw[];
    float* sH = s_raw;                  // 64*264 = 16896 floats
    float* sA = s_raw + 16896;          // [k][o] k<64: conv, k>=64: spectral; 128*64
    int bh = blockIdx.x;
    int b = bh / HP, h = bh - b * HP;
    bool last = (l == NL - 1);
    if (last && h >= H0) return;        // uniform per block
    int t = threadIdx.x;                // 264 threads
    const float* hb = g_h[cur];
    {
        for (int idx = t; idx < 64 * 66; idx += 264) {
            int i = idx / 66, c = idx - i * 66;
            reinterpret_cast<float4*>(sH)[i * 66 + c] =
                reinterpret_cast<const float4*>(
                    hb + (((size_t)b * CW + i) * HP + h) * WP)[c];
        }
    }
    const float* cwl = cw + (size_t)l * 4096;
    for (int r = t; r < 4096; r += 264) {
        int o = r >> 6, i = r & 63;
        sA[i * 64 + o] = cwl[r];
    }
    const float* yf = (const float*)g_y1;
    for (int r = t; r < 4096; r += 264) {
        int o = r >> 6, kk = r & 63;
        sA[(64 + kk) * 64 + o] = yf[(((size_t)b * CW + o) * HP + h) * 64 + kk];
    }
    __syncthreads();
    int mc = t & 3, wc = t >> 2;
    int obase = mc * 16, wbase = wc * 4;
    u64 acc2[8][4];
#pragma unroll
    for (int p = 0; p < 8; ++p)
#pragma unroll
        for (int w = 0; w < 4; ++w) acc2[p][w] = 0ull;
#pragma unroll 4
    for (int k = 0; k < 64; ++k) {      // conv part
        float4 bv = *reinterpret_cast<const float4*>(&sH[k * WP + wbase]);
        u64 bb0 = bcast2(bv.x), bb1 = bcast2(bv.y), bb2 = bcast2(bv.z), bb3 = bcast2(bv.w);
        const ulonglong2* pa = reinterpret_cast<const ulonglong2*>(&sA[k * 64 + obase]);
        ulonglong2 A0 = pa[0], A1 = pa[1], A2 = pa[2], A3 = pa[3];
        u64 ap[8] = {A0.x, A0.y, A1.x, A1.y, A2.x, A2.y, A3.x, A3.y};
#pragma unroll
        for (int p = 0; p < 8; ++p) {
            fma2(acc2[p][0], ap[p], bb0);
            fma2(acc2[p][1], ap[p], bb1);
            fma2(acc2[p][2], ap[p], bb2);
            fma2(acc2[p][3], ap[p], bb3);
        }
    }
#pragma unroll 4
    for (int k = 0; k < 64; ++k) {      // spectral part
        float4 bv = __ldg(reinterpret_cast<const float4*>(&g_aw[k * WP + wbase]));
        u64 bb0 = bcast2(bv.x), bb1 = bcast2(bv.y), bb2 = bcast2(bv.z), bb3 = bcast2(bv.w);
        const ulonglong2* pa = reinterpret_cast<const ulonglong2*>(&sA[(64 + k) * 64 + obase]);
        ulonglong2 A0 = pa[0], A1 = pa[1], A2 = pa[2], A3 = pa[3];
        u64 ap[8] = {A0.x, A0.y, A1.x, A1.y, A2.x, A2.y, A3.x, A3.y};
#pragma unroll
        for (int p = 0; p < 8; ++p) {
            fma2(acc2[p][0], ap[p], bb0);
            fma2(acc2[p][1], ap[p], bb1);
            fma2(acc2[p][2], ap[p], bb2);
            fma2(acc2[p][3], ap[p], bb3);
        }
    }
    float* hn = g_h[cur ^ 1];
#pragma unroll
    for (int p = 0; p < 8; ++p) {
        float2 e0 = up2(acc2[p][0]), e1 = up2(acc2[p][1]);
        float2 e2 = up2(acc2[p][2]), e3 = up2(acc2[p][3]);
        int o0 = obase + 2 * p;
        float bias0 = __ldg(&cb[l * 64 + o0]);
        float bias1 = __ldg(&cb[l * 64 + o0 + 1]);
        float4 v0 = make_float4(e0.x + bias0, e1.x + bias0, e2.x + bias0, e3.x + bias0);
        float4 v1 = make_float4(e0.y + bias1, e1.y + bias1, e2.y + bias1, e3.y + bias1);
        if (!last) {
            v0.x = gelu_f(v0.x); v0.y = gelu_f(v0.y); v0.z = gelu_f(v0.z); v0.w = gelu_f(v0.w);
            v1.x = gelu_f(v1.x); v1.y = gelu_f(v1.y); v1.z = gelu_f(v1.z); v1.w = gelu_f(v1.w);
            *reinterpret_cast<float4*>(
                &hn[(((size_t)b * CW + o0) * HP + h) * WP + wbase]) = v0;
            *reinterpret_cast<float4*>(
                &hn[(((size_t)b * CW + o0 + 1) * HP + h) * WP + wbase]) = v1;
        } else if (wbase < W0) {
            *reinterpret_cast<float4*>(
                &out[(((size_t)b * CW + o0) * H0 + h) * W0 + wbase]) = v0;
            *reinterpret_cast<float4*>(
                &out[(((size_t)b * CW + o0 + 1) * H0 + h) * W0 + wbase]) = v1;
        }
    }
}

// ---------------- launch ---------------------------------------------------
extern "C" void kernel_launch(void* const* d_in, const int* in_sizes, int n_in,
                              void* d_out, int out_size) {
    const float* x   = (const float*)d_in[0];
    const float* lw1 = (const float*)d_in[1];
    const float* lb1 = (const float*)d_in[2];
    const float* lw2 = (const float*)d_in[3];
    const float* lb2 = (const float*)d_in[4];
    const float* cw  = (const float*)d_in[5];
    const float* cb  = (const float*)d_in[6];
    const float* sp1 = (const float*)d_in[7];
    const float* sp2 = (const float*)d_in[8];
    float* out = (float*)d_out;

    const int SMEM_K1 = WP * 66 * 4;                  // 69696
    const int SMEM_K2 = HP * MW * 8;                  // 67584
    const int SMEM_K5 = (16896 + 128 * 64) * 4;       // 100352

    cudaFuncSetAttribute(k1_wdft,    cudaFuncAttributeMaxDynamicSharedMemorySize, SMEM_K1);
    cudaFuncSetAttribute(k2_hdft,    cudaFuncAttributeMaxDynamicSharedMemorySize, SMEM_K2);
    cudaFuncSetAttribute(k5_combine, cudaFuncAttributeMaxDynamicSharedMemorySize, SMEM_K5);

    k_init<<<66, 256>>>();
    k_zero<<<2048, 256>>>();
    k_lift<<<BATCH * 256, 256>>>(x, lw1, lb1, lw2, lb2);

    for (int l = 0; l < NL; ++l) {
        int cur = l & 1;
        k1_wdft<<<(BATCH * CW * HP) / 64, 256, SMEM_K1>>>(cur);
        k2_hdft<<<BATCH * CW, 256, SMEM_K2>>>();
        k3_mix<<<MH * 4, 256>>>(sp1, sp2, l);
        k4_invh<<<BATCH * CW, 256>>>();
        k5_combine<<<BATCH * HP, 264, SMEM_K5>>>(cur, cw, cb, l, out);
    }
}

// round 6
// speedup vs baseline: 2.0872x; 2.0872x over previous
#include <cuda_runtime.h>
#include <math.h>

#define BATCH 8
#define CW    64
#define H0    256
#define W0    256
#define HP    264
#define WP    264
#define MW    32      // kept kx modes
#define MH    64      // kept ky modes (32 top + 32 bottom)
#define NL    4
#define HW    (HP*WP)            // 69696
#define NPIX  (BATCH*CW*HW)      // 35684352

// ---------------- scratch (device globals; no allocation allowed) ----------
__device__ __align__(128) float  g_h[2][NPIX];              // 2 x 142.7 MB
__device__ __align__(128) float2 g_x1[BATCH*CW*HP*MW];      // 34.6 MB
__device__ __align__(128) float2 g_x2[BATCH*CW*MH*MW];      // 8.4 MB
__device__ __align__(128) float2 g_y2[BATCH*CW*MH*MW];      // 8.4 MB
__device__ __align__(128) float2 g_y1[BATCH*CW*HP*MW];      // 34.6 MB
__device__ __align__(128) float2 g_fw[WP*MW];               // [w][kx] (cos,-sin)
__device__ __align__(128) float2 g_fh[HP*MH];               // [h][j]  (cos,-sin)
__device__ __align__(128) float2 g_gh[HP*MH];               // [h][j]  (cos,+sin)
__device__ __align__(128) float2 g_awf[8*33*32 + 32];       // fragment-ordered c2r invW (tf32)

__device__ __forceinline__ float gelu_f(float v) {
    return 0.5f * v * (1.0f + erff(v * 0.70710678118654752f));
}

__device__ __forceinline__ float tf32r(float x) {
    float y;
    asm("cvt.rna.tf32.f32 %0, %1;" : "=f"(y) : "f"(x));
    return y;
}

// mma.m16n8k8 tf32: D += A(16x8,row) * B(8x8,col)
__device__ __forceinline__ void mma_tf32(float* d, unsigned a0, unsigned a1,
                                         unsigned a2, unsigned a3,
                                         unsigned b0, unsigned b1) {
    asm("mma.sync.aligned.m16n8k8.row.col.f32.tf32.tf32.f32 "
        "{%0,%1,%2,%3}, {%4,%5,%6,%7}, {%8,%9}, {%0,%1,%2,%3};"
        : "+f"(d[0]), "+f"(d[1]), "+f"(d[2]), "+f"(d[3])
        : "r"(a0), "r"(a1), "r"(a2), "r"(a3), "r"(b0), "r"(b1));
}

// ---------------- twiddle/matrix init (double-precision trig) --------------
__global__ void k_init() {
    int i = blockIdx.x * blockDim.x + threadIdx.x;
    if (i >= HP * MH) return;   // 16896
    const double TWO_PI = 6.283185307179586476925286766559;
    {   // g_fh / g_gh : [h][j]
        int h = i >> 6, j = i & 63;
        int ky = (j < 32) ? j : (j + (HP - MH));
        long m = ((long)h * (long)ky) % HP;
        double ang = TWO_PI * (double)m / (double)HP;
        double s, c; sincos(ang, &s, &c);
        g_fh[i] = make_float2((float)c, (float)(-s));
        g_gh[i] = make_float2((float)c, (float)( s));
    }
    if (i < WP * MW) {  // g_fw : [w][kx]
        int w = i >> 5, k = i & 31;
        long m = ((long)w * (long)k) % WP;
        double ang = TWO_PI * (double)m / (double)WP;
        double s, c; sincos(ang, &s, &c);
        g_fw[i] = make_float2((float)c, (float)(-s));
    }
    if (i < 8 * 33 * 32 + 32) {  // g_awf : fragment-ordered inverse-W, tf32-rounded
        float2 v = make_float2(0.f, 0.f);
        if (i < 8448) {
            int ktl = i / 1056, rem = i - ktl * 1056;
            int nt = rem >> 5, lane = rem & 31;
            int cc = lane & 3, rr = lane >> 2;
            int w = nt * 8 + rr;
#pragma unroll
            for (int half = 0; half < 2; ++half) {
                int kk = ktl * 8 + cc + 4 * half;
                int k = kk >> 1;
                double sc = ((k == 0) ? 1.0 : 2.0) / ((double)HP * (double)WP);
                long m = ((long)k * (long)w) % WP;
                double ang = TWO_PI * (double)m / (double)WP;
                double s, c; sincos(ang, &s, &c);
                float val = (float)((kk & 1) ? (-sc * s) : (sc * c));
                if (half == 0) v.x = tf32r(val); else v.y = tf32r(val);
            }
        }
        g_awf[i] = v;
    }
}

__global__ void k_zero() {
    float4* p = (float4*)g_h[0];
    size_t n4 = (size_t)NPIX / 4;
    for (size_t i = (size_t)blockIdx.x * blockDim.x + threadIdx.x; i < n4;
         i += (size_t)gridDim.x * blockDim.x)
        p[i] = make_float4(0.f, 0.f, 0.f, 0.f);
}

// ---------------- lift: [x, gx, gy] -> gelu(W1.) -> W2. -------------------
__global__ void k_lift(const float* __restrict__ x,
                       const float* __restrict__ w1, const float* __restrict__ b1,
                       const float* __restrict__ w2, const float* __restrict__ b2) {
    __shared__ float sw1[160], sb1[32], sw2[2048], sb2[64];
    int t = threadIdx.x;
    if (t < 160) sw1[t] = w1[t];
    if (t < 32)  sb1[t] = b1[t];
    for (int i = t; i < 2048; i += 256) sw2[i] = w2[i];
    if (t < 64)  sb2[t] = b2[t];
    __syncthreads();
    int b = blockIdx.x >> 8, h = blockIdx.x & 255, w = t;
    float in5[5];
#pragma unroll
    for (int c = 0; c < 3; ++c)
        in5[c] = x[(((size_t)b * 3 + c) * H0 + h) * W0 + w];
    in5[3] = (float)h * (1.0f / 255.0f);
    in5[4] = (float)w * (1.0f / 255.0f);
    float mid[32];
#pragma unroll
    for (int o = 0; o < 32; ++o) {
        float s = sb1[o];
#pragma unroll
        for (int i = 0; i < 5; ++i) s = fmaf(sw1[o * 5 + i], in5[i], s);
        mid[o] = gelu_f(s);
    }
    float* hb = g_h[0];
#pragma unroll 4
    for (int o = 0; o < 64; ++o) {
        float s = sb2[o];
#pragma unroll
        for (int i = 0; i < 32; ++i) s = fmaf(sw2[o * 32 + i], mid[i], s);
        hb[(((size_t)b * CW + o) * HP + h) * WP + w] = s;
    }
}

// ---------------- K1: partial rDFT along W  (h -> x1) ----------------------
__global__ __launch_bounds__(256) void k1_wdft(int cur) {
    __shared__ float sA[32 * WP];                        // 33792 B
    const float* hb = g_h[cur] + (size_t)blockIdx.x * 32 * WP;
    {
        const float4* src = reinterpret_cast<const float4*>(hb);
        float4* dst = reinterpret_cast<float4*>(sA);
        for (int i = threadIdx.x; i < (32 * WP) / 4; i += 256) dst[i] = src[i];
    }
    __syncthreads();
    int kx = threadIdx.x & 31, rb = threadIdx.x >> 5;    // warp rb: rows rb+8r
    float2 acc[4];
#pragma unroll
    for (int r = 0; r < 4; ++r) acc[r] = make_float2(0.f, 0.f);
#pragma unroll 2
    for (int w4 = 0; w4 < WP; w4 += 4) {
        float2 f0 = __ldg(&g_fw[(w4 + 0) * MW + kx]);
        float2 f1 = __ldg(&g_fw[(w4 + 1) * MW + kx]);
        float2 f2 = __ldg(&g_fw[(w4 + 2) * MW + kx]);
        float2 f3 = __ldg(&g_fw[(w4 + 3) * MW + kx]);
#pragma unroll
        for (int r = 0; r < 4; ++r) {
            float4 av = *reinterpret_cast<const float4*>(&sA[(rb + 8 * r) * WP + w4]);
            acc[r].x = fmaf(av.x, f0.x, acc[r].x);
            acc[r].y = fmaf(av.x, f0.y, acc[r].y);
            acc[r].x = fmaf(av.y, f1.x, acc[r].x);
            acc[r].y = fmaf(av.y, f1.y, acc[r].y);
            acc[r].x = fmaf(av.z, f2.x, acc[r].x);
            acc[r].y = fmaf(av.z, f2.y, acc[r].y);
            acc[r].x = fmaf(av.w, f3.x, acc[r].x);
            acc[r].y = fmaf(av.w, f3.y, acc[r].y);
        }
    }
    size_t row0 = (size_t)blockIdx.x * 32;
#pragma unroll
    for (int r = 0; r < 4; ++r)
        g_x1[(row0 + rb + 8 * r) * MW + kx] = acc[r];
}

// ---------------- K2: partial DFT along H  (x1 -> x2), complex -------------
__global__ void k2_hdft() {
    extern __shared__ float s_raw[];
    float2* sX = reinterpret_cast<float2*>(s_raw);       // [h][kx] 264x32
    int bc = blockIdx.x;
    const float4* src = reinterpret_cast<const float4*>(g_x1 + (size_t)bc * HP * MW);
    float4* dst = reinterpret_cast<float4*>(sX);
    for (int i = threadIdx.x; i < (HP * MW) / 2; i += 256) dst[i] = src[i];
    __syncthreads();
    int kx = threadIdx.x & 31, jg = threadIdx.x >> 5;    // jg: 0..7, 8 j's each
    float2 acc[8];
#pragma unroll
    for (int q = 0; q < 8; ++q) acc[q] = make_float2(0.f, 0.f);
#pragma unroll 2
    for (int h = 0; h < HP; ++h) {
        float2 xv = sX[h * MW + kx];
        const float4* f4 = reinterpret_cast<const float4*>(&g_fh[h * MH + jg * 8]);
        float4 A = __ldg(&f4[0]);
        float4 B = __ldg(&f4[1]);
        float4 C = __ldg(&f4[2]);
        float4 D = __ldg(&f4[3]);
#define CFMA2(fr, fi, q) \
        acc[q].x = fmaf((fr), xv.x, acc[q].x); acc[q].x = fmaf(-(fi), xv.y, acc[q].x); \
        acc[q].y = fmaf((fr), xv.y, acc[q].y); acc[q].y = fmaf((fi), xv.x, acc[q].y);
        CFMA2(A.x, A.y, 0) CFMA2(A.z, A.w, 1)
        CFMA2(B.x, B.y, 2) CFMA2(B.z, B.w, 3)
        CFMA2(C.x, C.y, 4) CFMA2(C.z, C.w, 5)
        CFMA2(D.x, D.y, 6) CFMA2(D.z, D.w, 7)
#undef CFMA2
    }
#pragma unroll
    for (int q = 0; q < 8; ++q)
        g_x2[((size_t)bc * MH + jg * 8 + q) * MW + kx] = acc[q];
}

// ---------------- K3: per-mode channel mixing (x2 -> y2) -------------------
__global__ __launch_bounds__(256) void k3_mix(const float* __restrict__ spw1,
                                              const float* __restrict__ spw2, int l) {
    __shared__ float2 sX[2 * 64 * 32];                   // [b2][i][kx] 32 KB
    int jj = blockIdx.x >> 2, bp = blockIdx.x & 3;
    int b0 = bp * 2;
    int t = threadIdx.x, kx = t & 31, sub = t >> 5;      // sub 0..7 -> o = sub*8+q
    for (int idx = t; idx < 4096; idx += 256) {
        int bi = idx >> 11, rest = idx & 2047;
        int i = rest >> 5, kxl = rest & 31;
        sX[idx] = g_x2[(((size_t)(b0 + bi) * CW + i) * MH + jj) * MW + kxl];
    }
    __syncthreads();
    const float2* wp; int jx;
    if (jj < 32) { wp = (const float2*)spw1; jx = jj; }
    else         { wp = (const float2*)spw2; jx = jj - 32; }
    size_t wbase = (size_t)l * 4194304 + (size_t)jx * 32 + kx;
    float2 a0[8], a1[8];
#pragma unroll
    for (int q = 0; q < 8; ++q) { a0[q] = make_float2(0.f, 0.f); a1[q] = make_float2(0.f, 0.f); }
#pragma unroll 2
    for (int i = 0; i < 64; ++i) {
        float2 x0 = sX[i * 32 + kx];
        float2 x1 = sX[2048 + i * 32 + kx];
        size_t row = wbase + (size_t)(i * 64 + sub * 8) * 1024;
#pragma unroll
        for (int q = 0; q < 8; ++q) {
            float2 c = __ldg(&wp[row + (size_t)q * 1024]);
            a0[q].x = fmaf(x0.x, c.x, a0[q].x); a0[q].x = fmaf(-x0.y, c.y, a0[q].x);
            a0[q].y = fmaf(x0.x, c.y, a0[q].y); a0[q].y = fmaf( x0.y, c.x, a0[q].y);
            a1[q].x = fmaf(x1.x, c.x, a1[q].x); a1[q].x = fmaf(-x1.y, c.y, a1[q].x);
            a1[q].y = fmaf(x1.x, c.y, a1[q].y); a1[q].y = fmaf( x1.y, c.x, a1[q].y);
        }
    }
#pragma unroll
    for (int q = 0; q < 8; ++q) {
        int o = sub * 8 + q;
        g_y2[(((size_t)b0       * CW + o) * MH + jj) * MW + kx] = a0[q];
        g_y2[(((size_t)(b0 + 1) * CW + o) * MH + jj) * MW + kx] = a1[q];
    }
}

// ---------------- K4: inverse DFT along H (y2 -> y1), complex, K=64 --------
__global__ void k4_invh() {
    __shared__ float2 sY[MH * MW];                       // 16 KB
    int bo = blockIdx.x;
    const float4* src = reinterpret_cast<const float4*>(g_y2 + (size_t)bo * MH * MW);
    float4* dst = reinterpret_cast<float4*>(sY);
    for (int i = threadIdx.x; i < (MH * MW) / 2; i += 256) dst[i] = src[i];
    __syncthreads();
    int kxp = threadIdx.x & 15, hg = threadIdx.x >> 4;   // kx pair, 16 h-groups
    int kx0 = kxp * 2;
    for (int k = 0; k < 17; ++k) {
        int h = k * 16 + hg;
        if (h < HP) {
            float2 a0 = make_float2(0.f, 0.f), a1 = make_float2(0.f, 0.f);
            const float4* g4 = reinterpret_cast<const float4*>(&g_gh[h * MH]);
#pragma unroll 8
            for (int j = 0; j < 64; j += 2) {
                float4 g2 = __ldg(&g4[j >> 1]);          // (c_j, s_j, c_j1, s_j1)
                float4 y0 = *reinterpret_cast<const float4*>(&sY[j * MW + kx0]);
                float4 y1v = *reinterpret_cast<const float4*>(&sY[(j + 1) * MW + kx0]);
                a0.x = fmaf(g2.x, y0.x, a0.x); a0.x = fmaf(-g2.y, y0.y, a0.x);
                a0.y = fmaf(g2.x, y0.y, a0.y); a0.y = fmaf( g2.y, y0.x, a0.y);
                a1.x = fmaf(g2.x, y0.z, a1.x); a1.x = fmaf(-g2.y, y0.w, a1.x);
                a1.y = fmaf(g2.x, y0.w, a1.y); a1.y = fmaf( g2.y, y0.z, a1.y);
                a0.x = fmaf(g2.z, y1v.x, a0.x); a0.x = fmaf(-g2.w, y1v.y, a0.x);
                a0.y = fmaf(g2.z, y1v.y, a0.y); a0.y = fmaf( g2.w, y1v.x, a0.y);
                a1.x = fmaf(g2.z, y1v.z, a1.x); a1.x = fmaf(-g2.w, y1v.w, a1.x);
                a1.y = fmaf(g2.z, y1v.w, a1.y); a1.y = fmaf( g2.w, y1v.z, a1.y);
            }
            float4 outv = make_float4(a0.x, a0.y, a1.x, a1.y);
            *reinterpret_cast<float4*>(&g_y1[((size_t)bo * HP + h) * MW + kx0]) = outv;
        }
    }
}

// ---------------- K5: tf32 mma GEMM: conv1x1 + inverse-W(c2r) + bias + gelu
// per (b,h): C[64 o][264 w] = sum_k A[o][k] B[k][w];  k<64 conv, k>=64 spectral
__global__ __launch_bounds__(256, 2)
void k5_combine(int cur, const float* __restrict__ cw,
                const float* __restrict__ cb, int l,
                float* __restrict__ out) {
    extern __shared__ float s_raw[];
    float* sAt = s_raw;                 // [o][k] stride 132, 64x132
    float* sB  = s_raw + 64 * 132;      // [k][w] stride 264, 65x264 (1 pad row)
    int bh = blockIdx.x;
    int b = bh / HP, h = bh - b * HP;
    bool last = (l == NL - 1);
    if (last && h >= H0) return;
    int t = threadIdx.x;
    // ---- stage B (conv half): h rows, tf32-rounded
    {
        const float* hb = g_h[cur] + ((size_t)b * CW * HP + h) * WP;
        const size_t rstride = (size_t)HP * WP;
        for (int idx = t; idx < 64 * 66; idx += 256) {
            int i = idx / 66, cq = idx - i * 66;
            float4 v = *reinterpret_cast<const float4*>(hb + (size_t)i * rstride + cq * 4);
            v.x = tf32r(v.x); v.y = tf32r(v.y); v.z = tf32r(v.z); v.w = tf32r(v.w);
            reinterpret_cast<float4*>(sB)[i * 66 + cq] = v;
        }
    }
    // ---- stage A: conv weights [o][i] and spectral coeffs [o][kk]
    {
        const float* cwl = cw + (size_t)l * 4096;
        for (int r2 = t; r2 < 4096; r2 += 256) {
            int o = r2 >> 6, i = r2 & 63;
            sAt[o * 132 + i] = tf32r(cwl[r2]);
        }
        const float* ybase = (const float*)g_y1 + ((size_t)b * CW * HP + h) * 64;
        for (int r2 = t; r2 < 4096; r2 += 256) {
            int o = r2 >> 6, kk = r2 & 63;
            sAt[o * 132 + 64 + kk] = tf32r(ybase[(size_t)o * (HP * 64) + kk]);
        }
    }
    __syncthreads();
    int lane = t & 31, wid = t >> 5;
    int mi = wid & 3, nh = wid >> 2;    // 4 m-tiles x 2 n-halves
    int m0 = mi * 16;
    int c = lane & 3, r = lane >> 2;
    int ntBeg = nh * 17;                // nh=0: tiles 0..16 ; nh=1: 17..32 (+1 pad)
    float acc[17][4];
#pragma unroll
    for (int j = 0; j < 17; ++j) {
        acc[j][0] = 0.f; acc[j][1] = 0.f; acc[j][2] = 0.f; acc[j][3] = 0.f;
    }
    int aRowBase = (m0 + r) * 132 + c;
    // ---- conv half: B from smem
#pragma unroll 2
    for (int kt = 0; kt < 8; ++kt) {
        int k0 = kt * 8;
        unsigned a0 = __float_as_uint(sAt[aRowBase + k0]);
        unsigned a1 = __float_as_uint(sAt[aRowBase + 8 * 132 + k0]);
        unsigned a2 = __float_as_uint(sAt[aRowBase + k0 + 4]);
        unsigned a3 = __float_as_uint(sAt[aRowBase + 8 * 132 + k0 + 4]);
        int bRow = (k0 + c) * 264 + r + ntBeg * 8;
#pragma unroll
        for (int j = 0; j < 17; ++j) {
            unsigned b0 = __float_as_uint(sB[bRow + j * 8]);
            unsigned b1 = __float_as_uint(sB[bRow + 4 * 264 + j * 8]);
            mma_tf32(acc[j], a0, a1, a2, a3, b0, b1);
        }
    }
    // ---- spectral half: B fragments pre-swizzled in g_awf (tf32)
#pragma unroll 2
    for (int kt = 8; kt < 16; ++kt) {
        int k0 = kt * 8;
        unsigned a0 = __float_as_uint(sAt[aRowBase + k0]);
        unsigned a1 = __float_as_uint(sAt[aRowBase + 8 * 132 + k0]);
        unsigned a2 = __float_as_uint(sAt[aRowBase + k0 + 4]);
        unsigned a3 = __float_as_uint(sAt[aRowBase + 8 * 132 + k0 + 4]);
        const float2* bp = &g_awf[(((kt - 8) * 33) + ntBeg) * 32 + lane];
#pragma unroll
        for (int j = 0; j < 17; ++j) {
            float2 bb = __ldg(&bp[j * 32]);
            mma_tf32(acc[j], a0, a1, a2, a3,
                     __float_as_uint(bb.x), __float_as_uint(bb.y));
        }
    }
    // ---- epilogue: bias + gelu + store
    int o0 = m0 + r, o1 = o0 + 8;
    float bias0 = __ldg(&cb[l * 64 + o0]);
    float bias1 = __ldg(&cb[l * 64 + o1]);
    float* hn = g_h[cur ^ 1];
#pragma unroll
    for (int j = 0; j < 17; ++j) {
        if (nh && j == 16) continue;                 // pad tile
        int n0 = (ntBeg + j) * 8;
        int wcol = n0 + 2 * c;
        float2 p0 = make_float2(acc[j][0] + bias0, acc[j][1] + bias0);
        float2 p1 = make_float2(acc[j][2] + bias1, acc[j][3] + bias1);
        if (!last) {
            p0.x = gelu_f(p0.x); p0.y = gelu_f(p0.y);
            p1.x = gelu_f(p1.x); p1.y = gelu_f(p1.y);
            *reinterpret_cast<float2*>(
                &hn[(((size_t)b * CW + o0) * HP + h) * WP + wcol]) = p0;
            *reinterpret_cast<float2*>(
                &hn[(((size_t)b * CW + o1) * HP + h) * WP + wcol]) = p1;
        } else if (n0 < W0) {
            *reinterpret_cast<float2*>(
                &out[(((size_t)b * CW + o0) * H0 + h) * W0 + wcol]) = p0;
            *reinterpret_cast<float2*>(
                &out[(((size_t)b * CW + o1) * H0 + h) * W0 + wcol]) = p1;
        }
    }
}

// ---------------- launch ---------------------------------------------------
extern "C" void kernel_launch(void* const* d_in, const int* in_sizes, int n_in,
                              void* d_out, int out_size) {
    const float* x   = (const float*)d_in[0];
    const float* lw1 = (const float*)d_in[1];
    const float* lb1 = (const float*)d_in[2];
    const float* lw2 = (const float*)d_in[3];
    const float* lb2 = (const float*)d_in[4];
    const float* cw  = (const float*)d_in[5];
    const float* cb  = (const float*)d_in[6];
    const float* sp1 = (const float*)d_in[7];
    const float* sp2 = (const float*)d_in[8];
    float* out = (float*)d_out;

    const int SMEM_K2 = HP * MW * 8;                       // 67584
    const int SMEM_K5 = (64 * 132 + 65 * 264) * 4;         // 33792*... = 102432 B

    cudaFuncSetAttribute(k2_hdft,    cudaFuncAttributeMaxDynamicSharedMemorySize, SMEM_K2);
    cudaFuncSetAttribute(k5_combine, cudaFuncAttributeMaxDynamicSharedMemorySize, SMEM_K5);

    k_init<<<66, 256>>>();
    k_zero<<<2048, 256>>>();
    k_lift<<<BATCH * 256, 256>>>(x, lw1, lb1, lw2, lb2);

    for (int l = 0; l < NL; ++l) {
        int cur = l & 1;
        k1_wdft<<<(BATCH * CW * HP) / 32, 256>>>(cur);
        k2_hdft<<<BATCH * CW, 256, SMEM_K2>>>();
        k3_mix<<<MH * 4, 256>>>(sp1, sp2, l);
        k4_invh<<<BATCH * CW, 256>>>();
        k5_combine<<<BATCH * HP, 256, SMEM_K5>>>(cur, cw, cb, l, out);
    }
}

// round 7
// speedup vs baseline: 2.2751x; 1.0900x over previous
#include <cuda_runtime.h>
#include <math.h>

#define BATCH 8
#define CW    64
#define H0    256
#define W0    256
#define HP    264
#define WP    264
#define MW    32      // kept kx modes
#define MH    64      // kept ky modes (32 top + 32 bottom)
#define NL    4
#define HW    (HP*WP)            // 69696
#define NPIX  (BATCH*CW*HW)      // 35684352

// ---------------- scratch (device globals; no allocation allowed) ----------
__device__ __align__(128) float  g_h[2][NPIX];              // 2 x 142.7 MB
__device__ __align__(128) float2 g_x1[BATCH*CW*HP*MW];      // 34.6 MB
__device__ __align__(128) float2 g_x2[BATCH*CW*MH*MW];      // 8.4 MB
__device__ __align__(128) float2 g_y2[BATCH*CW*MH*MW];      // 8.4 MB
__device__ __align__(128) float2 g_y1[BATCH*CW*HP*MW];      // 34.6 MB
__device__ __align__(128) float2 g_fh[HP*MH];               // [h][j]  (cos,-sin)
__device__ __align__(128) float2 g_gh[HP*MH];               // [h][j]  (cos,+sin)
__device__ __align__(128) float2 g_awf[8*33*32 + 32];       // frag-ordered c2r invW (tf32)
__device__ __align__(128) float2 g_fwf[33*8*32];            // frag-ordered W-DFT B (tf32)

__device__ __forceinline__ float gelu_f(float v) {
    return 0.5f * v * (1.0f + erff(v * 0.70710678118654752f));
}

__device__ __forceinline__ float tf32r(float x) {
    float y;
    asm("cvt.rna.tf32.f32 %0, %1;" : "=f"(y) : "f"(x));
    return y;
}

// mma.m16n8k8 tf32: D += A(16x8,row) * B(8x8,col)
__device__ __forceinline__ void mma_tf32(float* d, unsigned a0, unsigned a1,
                                         unsigned a2, unsigned a3,
                                         unsigned b0, unsigned b1) {
    asm("mma.sync.aligned.m16n8k8.row.col.f32.tf32.tf32.f32 "
        "{%0,%1,%2,%3}, {%4,%5,%6,%7}, {%8,%9}, {%0,%1,%2,%3};"
        : "+f"(d[0]), "+f"(d[1]), "+f"(d[2]), "+f"(d[3])
        : "r"(a0), "r"(a1), "r"(a2), "r"(a3), "r"(b0), "r"(b1));
}

// ---------------- twiddle/matrix init (double-precision trig) --------------
__global__ void k_init() {
    int i = blockIdx.x * blockDim.x + threadIdx.x;
    if (i >= HP * MH) return;   // 16896
    const double TWO_PI = 6.283185307179586476925286766559;
    {   // g_fh / g_gh : [h][j]
        int h = i >> 6, j = i & 63;
        int ky = (j < 32) ? j : (j + (HP - MH));
        long m = ((long)h * (long)ky) % HP;
        double ang = TWO_PI * (double)m / (double)HP;
        double s, c; sincos(ang, &s, &c);
        g_fh[i] = make_float2((float)c, (float)(-s));
        g_gh[i] = make_float2((float)c, (float)( s));
    }
    if (i < 33 * 8 * 32) {  // g_fwf : fragment-ordered W-DFT matrix, tf32
        int kt = i >> 8, rem = i & 255;
        int nt = rem >> 5, lane = rem & 31;
        int c = lane & 3, r = lane >> 2;
        int n = nt * 8 + r, kx = n >> 1, p = n & 1;
        float2 v;
#pragma unroll
        for (int half = 0; half < 2; ++half) {
            int w = kt * 8 + c + 4 * half;
            long m = ((long)w * (long)kx) % WP;
            double ang = TWO_PI * (double)m / (double)WP;
            double s, cs; sincos(ang, &s, &cs);
            float val = p ? (float)(-s) : (float)cs;
            if (half == 0) v.x = tf32r(val); else v.y = tf32r(val);
        }
        g_fwf[i] = v;
    }
    if (i < 8 * 33 * 32 + 32) {  // g_awf : fragment-ordered inverse-W, tf32
        float2 v = make_float2(0.f, 0.f);
        if (i < 8448) {
            int ktl = i / 1056, rem = i - ktl * 1056;
            int nt = rem >> 5, lane = rem & 31;
            int cc = lane & 3, rr = lane >> 2;
            int w = nt * 8 + rr;
#pragma unroll
            for (int half = 0; half < 2; ++half) {
                int kk = ktl * 8 + cc + 4 * half;
                int k = kk >> 1;
                double sc = ((k == 0) ? 1.0 : 2.0) / ((double)HP * (double)WP);
                long m = ((long)k * (long)w) % WP;
                double ang = TWO_PI * (double)m / (double)WP;
                double s, c; sincos(ang, &s, &c);
                float val = (float)((kk & 1) ? (-sc * s) : (sc * c));
                if (half == 0) v.x = tf32r(val); else v.y = tf32r(val);
            }
        }
        g_awf[i] = v;
    }
}

__global__ void k_zero() {
    float4* p = (float4*)g_h[0];
    size_t n4 = (size_t)NPIX / 4;
    for (size_t i = (size_t)blockIdx.x * blockDim.x + threadIdx.x; i < n4;
         i += (size_t)gridDim.x * blockDim.x)
        p[i] = make_float4(0.f, 0.f, 0.f, 0.f);
}

// ---------------- lift: [x, gx, gy] -> gelu(W1.) -> W2. -------------------
__global__ void k_lift(const float* __restrict__ x,
                       const float* __restrict__ w1, const float* __restrict__ b1,
                       const float* __restrict__ w2, const float* __restrict__ b2) {
    __shared__ float sw1[160], sb1[32], sw2[2048], sb2[64];
    int t = threadIdx.x;
    if (t < 160) sw1[t] = w1[t];
    if (t < 32)  sb1[t] = b1[t];
    for (int i = t; i < 2048; i += 256) sw2[i] = w2[i];
    if (t < 64)  sb2[t] = b2[t];
    __syncthreads();
    int b = blockIdx.x >> 8, h = blockIdx.x & 255, w = t;
    float in5[5];
#pragma unroll
    for (int c = 0; c < 3; ++c)
        in5[c] = x[(((size_t)b * 3 + c) * H0 + h) * W0 + w];
    in5[3] = (float)h * (1.0f / 255.0f);
    in5[4] = (float)w * (1.0f / 255.0f);
    float mid[32];
#pragma unroll
    for (int o = 0; o < 32; ++o) {
        float s = sb1[o];
#pragma unroll
        for (int i = 0; i < 5; ++i) s = fmaf(sw1[o * 5 + i], in5[i], s);
        mid[o] = gelu_f(s);
    }
    float* hb = g_h[0];
#pragma unroll 4
    for (int o = 0; o < 64; ++o) {
        float s = sb2[o];
#pragma unroll
        for (int i = 0; i < 32; ++i) s = fmaf(sw2[o * 32 + i], mid[i], s);
        hb[(((size_t)b * CW + o) * HP + h) * WP + w] = s;
    }
}

// ---------------- K1: partial rDFT along W via tf32 mma --------------------
// C[64 rows][64 cols] per block; col 2kx=re, 2kx+1=im; B const (g_fwf).
__global__ __launch_bounds__(256, 2) void k1_wdft(int cur) {
    extern __shared__ float sA[];                        // [64][268] 68608 B
    const float* hb = g_h[cur] + (size_t)blockIdx.x * 64 * WP;
    for (int idx = threadIdx.x; idx < 64 * 66; idx += 256) {
        int i = idx / 66, cq = idx - i * 66;
        float4 v = *reinterpret_cast<const float4*>(hb + (size_t)i * WP + cq * 4);
        v.x = tf32r(v.x); v.y = tf32r(v.y); v.z = tf32r(v.z); v.w = tf32r(v.w);
        *reinterpret_cast<float4*>(&sA[i * 268 + cq * 4]) = v;
    }
    __syncthreads();
    int lane = threadIdx.x & 31, wid = threadIdx.x >> 5;
    int mi = wid & 3, nh = wid >> 2;                     // 4 m-tiles x 2 n-halves
    int m0 = mi * 16;
    int c = lane & 3, r = lane >> 2;
    float acc[4][4];
#pragma unroll
    for (int j = 0; j < 4; ++j) {
        acc[j][0] = 0.f; acc[j][1] = 0.f; acc[j][2] = 0.f; acc[j][3] = 0.f;
    }
    int aRowBase = (m0 + r) * 268 + c;
#pragma unroll 3
    for (int kt = 0; kt < 33; ++kt) {
        int k0 = kt * 8;
        unsigned a0 = __float_as_uint(sA[aRowBase + k0]);
        unsigned a1 = __float_as_uint(sA[aRowBase + 8 * 268 + k0]);
        unsigned a2 = __float_as_uint(sA[aRowBase + k0 + 4]);
        unsigned a3 = __float_as_uint(sA[aRowBase + 8 * 268 + k0 + 4]);
        const float2* bp = &g_fwf[((kt * 8) + nh * 4) * 32 + lane];
#pragma unroll
        for (int j = 0; j < 4; ++j) {
            float2 bb = __ldg(&bp[j * 32]);
            mma_tf32(acc[j], a0, a1, a2, a3,
                     __float_as_uint(bb.x), __float_as_uint(bb.y));
        }
    }
    size_t row0 = (size_t)blockIdx.x * 64 + m0 + r;
#pragma unroll
    for (int j = 0; j < 4; ++j) {
        int kx = (nh * 4 + j) * 4 + c;
        g_x1[row0 * MW + kx]       = make_float2(acc[j][0], acc[j][1]);
        g_x1[(row0 + 8) * MW + kx] = make_float2(acc[j][2], acc[j][3]);
    }
}

// ---------------- K2: partial DFT along H  (x1 -> x2), complex -------------
__global__ void k2_hdft() {
    extern __shared__ float s_raw[];
    float2* sX = reinterpret_cast<float2*>(s_raw);       // [h][kx] 264x32
    int bc = blockIdx.x;
    const float4* src = reinterpret_cast<const float4*>(g_x1 + (size_t)bc * HP * MW);
    float4* dst = reinterpret_cast<float4*>(sX);
    for (int i = threadIdx.x; i < (HP * MW) / 2; i += 256) dst[i] = src[i];
    __syncthreads();
    int kx = threadIdx.x & 31, jg = threadIdx.x >> 5;    // jg: 0..7, 8 j's each
    float2 acc[8];
#pragma unroll
    for (int q = 0; q < 8; ++q) acc[q] = make_float2(0.f, 0.f);
#pragma unroll 2
    for (int h = 0; h < HP; ++h) {
        float2 xv = sX[h * MW + kx];
        const float4* f4 = reinterpret_cast<const float4*>(&g_fh[h * MH + jg * 8]);
        float4 A = __ldg(&f4[0]);
        float4 B = __ldg(&f4[1]);
        float4 C = __ldg(&f4[2]);
        float4 D = __ldg(&f4[3]);
#define CFMA2(fr, fi, q) \
        acc[q].x = fmaf((fr), xv.x, acc[q].x); acc[q].x = fmaf(-(fi), xv.y, acc[q].x); \
        acc[q].y = fmaf((fr), xv.y, acc[q].y); acc[q].y = fmaf((fi), xv.x, acc[q].y);
        CFMA2(A.x, A.y, 0) CFMA2(A.z, A.w, 1)
        CFMA2(B.x, B.y, 2) CFMA2(B.z, B.w, 3)
        CFMA2(C.x, C.y, 4) CFMA2(C.z, C.w, 5)
        CFMA2(D.x, D.y, 6) CFMA2(D.z, D.w, 7)
#undef CFMA2
    }
#pragma unroll
    for (int q = 0; q < 8; ++q)
        g_x2[((size_t)bc * MH + jg * 8 + q) * MW + kx] = acc[q];
}

// ---------------- K3: per-mode channel mixing (x2 -> y2) -------------------
__global__ __launch_bounds__(256) void k3_mix(const float* __restrict__ spw1,
                                              const float* __restrict__ spw2, int l) {
    __shared__ float2 sX[2 * 64 * 32];                   // [b2][i][kx] 32 KB
    int jj = blockIdx.x >> 2, bp = blockIdx.x & 3;
    int b0 = bp * 2;
    int t = threadIdx.x, kx = t & 31, sub = t >> 5;      // sub 0..7 -> o = sub*8+q
    for (int idx = t; idx < 4096; idx += 256) {
        int bi = idx >> 11, rest = idx & 2047;
        int i = rest >> 5, kxl = rest & 31;
        sX[idx] = g_x2[(((size_t)(b0 + bi) * CW + i) * MH + jj) * MW + kxl];
    }
    __syncthreads();
    const float2* wp; int jx;
    if (jj < 32) { wp = (const float2*)spw1; jx = jj; }
    else         { wp = (const float2*)spw2; jx = jj - 32; }
    size_t wbase = (size_t)l * 4194304 + (size_t)jx * 32 + kx;
    float2 a0[8], a1[8];
#pragma unroll
    for (int q = 0; q < 8; ++q) { a0[q] = make_float2(0.f, 0.f); a1[q] = make_float2(0.f, 0.f); }
#pragma unroll 2
    for (int i = 0; i < 64; ++i) {
        float2 x0 = sX[i * 32 + kx];
        float2 x1 = sX[2048 + i * 32 + kx];
        size_t row = wbase + (size_t)(i * 64 + sub * 8) * 1024;
#pragma unroll
        for (int q = 0; q < 8; ++q) {
            float2 c = __ldg(&wp[row + (size_t)q * 1024]);
            a0[q].x = fmaf(x0.x, c.x, a0[q].x); a0[q].x = fmaf(-x0.y, c.y, a0[q].x);
            a0[q].y = fmaf(x0.x, c.y, a0[q].y); a0[q].y = fmaf( x0.y, c.x, a0[q].y);
            a1[q].x = fmaf(x1.x, c.x, a1[q].x); a1[q].x = fmaf(-x1.y, c.y, a1[q].x);
            a1[q].y = fmaf(x1.x, c.y, a1[q].y); a1[q].y = fmaf( x1.y, c.x, a1[q].y);
        }
    }
#pragma unroll
    for (int q = 0; q < 8; ++q) {
        int o = sub * 8 + q;
        g_y2[(((size_t)b0       * CW + o) * MH + jj) * MW + kx] = a0[q];
        g_y2[(((size_t)(b0 + 1) * CW + o) * MH + jj) * MW + kx] = a1[q];
    }
}

// ---------------- K4: inverse DFT along H (y2 -> y1), complex, K=64 --------
__global__ void k4_invh() {
    __shared__ float2 sY[MH * MW];                       // 16 KB
    int bo = blockIdx.x;
    const float4* src = reinterpret_cast<const float4*>(g_y2 + (size_t)bo * MH * MW);
    float4* dst = reinterpret_cast<float4*>(sY);
    for (int i = threadIdx.x; i < (MH * MW) / 2; i += 256) dst[i] = src[i];
    __syncthreads();
    int kxp = threadIdx.x & 15, hg = threadIdx.x >> 4;   // kx pair, 16 h-groups
    int kx0 = kxp * 2;
    for (int k = 0; k < 17; ++k) {
        int h = k * 16 + hg;
        if (h < HP) {
            float2 a0 = make_float2(0.f, 0.f), a1 = make_float2(0.f, 0.f);
            const float4* g4 = reinterpret_cast<const float4*>(&g_gh[h * MH]);
#pragma unroll 8
            for (int j = 0; j < 64; j += 2) {
                float4 g2 = __ldg(&g4[j >> 1]);          // (c_j, s_j, c_j1, s_j1)
                float4 y0 = *reinterpret_cast<const float4*>(&sY[j * MW + kx0]);
                float4 y1v = *reinterpret_cast<const float4*>(&sY[(j + 1) * MW + kx0]);
                a0.x = fmaf(g2.x, y0.x, a0.x); a0.x = fmaf(-g2.y, y0.y, a0.x);
                a0.y = fmaf(g2.x, y0.y, a0.y); a0.y = fmaf( g2.y, y0.x, a0.y);
                a1.x = fmaf(g2.x, y0.z, a1.x); a1.x = fmaf(-g2.y, y0.w, a1.x);
                a1.y = fmaf(g2.x, y0.w, a1.y); a1.y = fmaf( g2.y, y0.z, a1.y);
                a0.x = fmaf(g2.z, y1v.x, a0.x); a0.x = fmaf(-g2.w, y1v.y, a0.x);
                a0.y = fmaf(g2.z, y1v.y, a0.y); a0.y = fmaf( g2.w, y1v.x, a0.y);
                a1.x = fmaf(g2.z, y1v.z, a1.x); a1.x = fmaf(-g2.w, y1v.w, a1.x);
                a1.y = fmaf(g2.z, y1v.w, a1.y); a1.y = fmaf( g2.w, y1v.z, a1.y);
            }
            float4 outv = make_float4(a0.x, a0.y, a1.x, a1.y);
            *reinterpret_cast<float4*>(&g_y1[((size_t)bo * HP + h) * MW + kx0]) = outv;
        }
    }
}

// ---------------- K5: tf32 mma GEMM: conv1x1 + inverse-W(c2r) + bias + gelu
__global__ __launch_bounds__(256, 2)
void k5_combine(int cur, const float* __restrict__ cw,
                const float* __restrict__ cb, int l,
                float* __restrict__ out) {
    extern __shared__ float s_raw[];
    float* sAt = s_raw;                 // [o][k] stride 132, 64x132
    float* sB  = s_raw + 64 * 132;      // [k][w] stride 264, 65x264 (1 pad row)
    int bh = blockIdx.x;
    int b = bh / HP, h = bh - b * HP;
    bool last = (l == NL - 1);
    if (last && h >= H0) return;
    int t = threadIdx.x;
    {
        const float* hb = g_h[cur] + ((size_t)b * CW * HP + h) * WP;
        const size_t rstride = (size_t)HP * WP;
        for (int idx = t; idx < 64 * 66; idx += 256) {
            int i = idx / 66, cq = idx - i * 66;
            float4 v = *reinterpret_cast<const float4*>(hb + (size_t)i * rstride + cq * 4);
            v.x = tf32r(v.x); v.y = tf32r(v.y); v.z = tf32r(v.z); v.w = tf32r(v.w);
            reinterpret_cast<float4*>(sB)[i * 66 + cq] = v;
        }
    }
    {
        const float* cwl = cw + (size_t)l * 4096;
        for (int r2 = t; r2 < 4096; r2 += 256) {
            int o = r2 >> 6, i = r2 & 63;
            sAt[o * 132 + i] = tf32r(cwl[r2]);
        }
        const float* ybase = (const float*)g_y1 + ((size_t)b * CW * HP + h) * 64;
        for (int r2 = t; r2 < 4096; r2 += 256) {
            int o = r2 >> 6, kk = r2 & 63;
            sAt[o * 132 + 64 + kk] = tf32r(ybase[(size_t)o * (HP * 64) + kk]);
        }
    }
    __syncthreads();
    int lane = t & 31, wid = t >> 5;
    int mi = wid & 3, nh = wid >> 2;    // 4 m-tiles x 2 n-halves
    int m0 = mi * 16;
    int c = lane & 3, r = lane >> 2;
    int ntBeg = nh * 17;                // nh=0: tiles 0..16 ; nh=1: 17..32 (+1 pad)
    float acc[17][4];
#pragma unroll
    for (int j = 0; j < 17; ++j) {
        acc[j][0] = 0.f; acc[j][1] = 0.f; acc[j][2] = 0.f; acc[j][3] = 0.f;
    }
    int aRowBase = (m0 + r) * 132 + c;
#pragma unroll 2
    for (int kt = 0; kt < 8; ++kt) {
        int k0 = kt * 8;
        unsigned a0 = __float_as_uint(sAt[aRowBase + k0]);
        unsigned a1 = __float_as_uint(sAt[aRowBase + 8 * 132 + k0]);
        unsigned a2 = __float_as_uint(sAt[aRowBase + k0 + 4]);
        unsigned a3 = __float_as_uint(sAt[aRowBase + 8 * 132 + k0 + 4]);
        int bRow = (k0 + c) * 264 + r + ntBeg * 8;
#pragma unroll
        for (int j = 0; j < 17; ++j) {
            unsigned b0 = __float_as_uint(sB[bRow + j * 8]);
            unsigned b1 = __float_as_uint(sB[bRow + 4 * 264 + j * 8]);
            mma_tf32(acc[j], a0, a1, a2, a3, b0, b1);
        }
    }
#pragma unroll 2
    for (int kt = 8; kt < 16; ++kt) {
        int k0 = kt * 8;
        unsigned a0 = __float_as_uint(sAt[aRowBase + k0]);
        unsigned a1 = __float_as_uint(sAt[aRowBase + 8 * 132 + k0]);
        unsigned a2 = __float_as_uint(sAt[aRowBase + k0 + 4]);
        unsigned a3 = __float_as_uint(sAt[aRowBase + 8 * 132 + k0 + 4]);
        const float2* bp = &g_awf[(((kt - 8) * 33) + ntBeg) * 32 + lane];
#pragma unroll
        for (int j = 0; j < 17; ++j) {
            float2 bb = __ldg(&bp[j * 32]);
            mma_tf32(acc[j], a0, a1, a2, a3,
                     __float_as_uint(bb.x), __float_as_uint(bb.y));
        }
    }
    int o0 = m0 + r, o1 = o0 + 8;
    float bias0 = __ldg(&cb[l * 64 + o0]);
    float bias1 = __ldg(&cb[l * 64 + o1]);
    float* hn = g_h[cur ^ 1];
#pragma unroll
    for (int j = 0; j < 17; ++j) {
        if (nh && j == 16) continue;                 // pad tile
        int n0 = (ntBeg + j) * 8;
        int wcol = n0 + 2 * c;
        float2 p0 = make_float2(acc[j][0] + bias0, acc[j][1] + bias0);
        float2 p1 = make_float2(acc[j][2] + bias1, acc[j][3] + bias1);
        if (!last) {
            p0.x = gelu_f(p0.x); p0.y = gelu_f(p0.y);
            p1.x = gelu_f(p1.x); p1.y = gelu_f(p1.y);
            *reinterpret_cast<float2*>(
                &hn[(((size_t)b * CW + o0) * HP + h) * WP + wcol]) = p0;
            *reinterpret_cast<float2*>(
                &hn[(((size_t)b * CW + o1) * HP + h) * WP + wcol]) = p1;
        } else if (n0 < W0) {
            *reinterpret_cast<float2*>(
                &out[(((size_t)b * CW + o0) * H0 + h) * W0 + wcol]) = p0;
            *reinterpret_cast<float2*>(
                &out[(((size_t)b * CW + o1) * H0 + h) * W0 + wcol]) = p1;
        }
    }
}

// ---------------- launch ---------------------------------------------------
extern "C" void kernel_launch(void* const* d_in, const int* in_sizes, int n_in,
                              void* d_out, int out_size) {
    const float* x   = (const float*)d_in[0];
    const float* lw1 = (const float*)d_in[1];
    const float* lb1 = (const float*)d_in[2];
    const float* lw2 = (const float*)d_in[3];
    const float* lb2 = (const float*)d_in[4];
    const float* cw  = (const float*)d_in[5];
    const float* cb  = (const float*)d_in[6];
    const float* sp1 = (const float*)d_in[7];
    const float* sp2 = (const float*)d_in[8];
    float* out = (float*)d_out;

    const int SMEM_K1 = 64 * 268 * 4;                      // 68608
    const int SMEM_K2 = HP * MW * 8;                       // 67584
    const int SMEM_K5 = (64 * 132 + 65 * 264) * 4;         // 102432

    cudaFuncSetAttribute(k1_wdft,    cudaFuncAttributeMaxDynamicSharedMemorySize, SMEM_K1);
    cudaFuncSetAttribute(k2_hdft,    cudaFuncAttributeMaxDynamicSharedMemorySize, SMEM_K2);
    cudaFuncSetAttribute(k5_combine, cudaFuncAttributeMaxDynamicSharedMemorySize, SMEM_K5);

    k_init<<<66, 256>>>();
    k_zero<<<2048, 256>>>();
    k_lift<<<BATCH * 256, 256>>>(x, lw1, lb1, lw2, lb2);

    for (int l = 0; l < NL; ++l) {
        int cur = l & 1;
        k1_wdft<<<(BATCH * CW * HP) / 64, 256, SMEM_K1>>>(cur);
        k2_hdft<<<BATCH * CW, 256, SMEM_K2>>>();
        k3_mix<<<MH * 4, 256>>>(sp1, sp2, l);
        k4_invh<<<BATCH * CW, 256>>>();
        k5_combine<<<BATCH * HP, 256, SMEM_K5>>>(cur, cw, cb, l, out);
    }
}

// round 8
// speedup vs baseline: 3.4087x; 1.4982x over previous
#include <cuda_runtime.h>
#include <math.h>

#define BATCH 8
#define CW    64
#define H0    256
#define W0    256
#define HP    264
#define WP    264
#define MW    32      // kept kx modes
#define MH    64      // kept ky modes (32 top + 32 bottom)
#define NL    4
#define HW    (HP*WP)            // 69696
#define NPIX  (BATCH*CW*HW)      // 35684352

// ---------------- scratch (device globals; no allocation allowed) ----------
__device__ __align__(128) float  g_h[2][NPIX];              // 2 x 142.7 MB
__device__ __align__(128) float2 g_x1[BATCH*CW*HP*MW];      // 34.6 MB
__device__ __align__(128) float  g_x2r[BATCH*CW*128*32];    // 8.4 MB (split re/im rows)
__device__ __align__(128) float2 g_y2[BATCH*CW*MH*MW];      // 8.4 MB
__device__ __align__(128) float  g_y1n[BATCH*HP*64*64];     // 34.6 MB [b][h][o][kk]
__device__ __align__(128) float2 g_awf[8*33*32 + 32];       // frag-ordered c2r invW (tf32)
__device__ __align__(128) float2 g_fwf[33*8*32];            // frag-ordered W-DFT B (tf32)
__device__ __align__(128) float4 g_fhf[8*66*32];            // frag-ordered H-DFT A (tf32)
__device__ __align__(128) float4 g_ghf[33*16*32];           // frag-ordered invH A (tf32)

__device__ __forceinline__ float gelu_f(float v) {
    return 0.5f * v * (1.0f + erff(v * 0.70710678118654752f));
}

__device__ __forceinline__ float tf32r(float x) {
    float y;
    asm("cvt.rna.tf32.f32 %0, %1;" : "=f"(y) : "f"(x));
    return y;
}

// mma.m16n8k8 tf32: D += A(16x8,row) * B(8x8,col)
__device__ __forceinline__ void mma_tf32(float* d, unsigned a0, unsigned a1,
                                         unsigned a2, unsigned a3,
                                         unsigned b0, unsigned b1) {
    asm("mma.sync.aligned.m16n8k8.row.col.f32.tf32.tf32.f32 "
        "{%0,%1,%2,%3}, {%4,%5,%6,%7}, {%8,%9}, {%0,%1,%2,%3};"
        : "+f"(d[0]), "+f"(d[1]), "+f"(d[2]), "+f"(d[3])
        : "r"(a0), "r"(a1), "r"(a2), "r"(a3), "r"(b0), "r"(b1));
}

#define TWO_PI_D 6.283185307179586476925286766559

// A entry for H-DFT: rows j' (2j+pj), cols k' (2h+ph)
__device__ float afh_val(int jp, int kp) {
    int j = jp >> 1, pj = jp & 1, h = kp >> 1, ph = kp & 1;
    int ky = (j < 32) ? j : j + (HP - MH);
    long m = ((long)h * (long)ky) % HP;
    double ang = TWO_PI_D * (double)m / (double)HP;
    double s, c; sincos(ang, &s, &c);
    double v = pj ? (ph ? c : -s) : (ph ? s : c);
    return tf32r((float)v);
}

// A entry for inverse-H: rows h' (2h+ph), cols j' (2j+pj)
__device__ float agh_val(int hpp, int jp) {
    int h = hpp >> 1, ph = hpp & 1, j = jp >> 1, pj = jp & 1;
    int ky = (j < 32) ? j : j + (HP - MH);
    long m = ((long)h * (long)ky) % HP;
    double ang = TWO_PI_D * (double)m / (double)HP;
    double s, c; sincos(ang, &s, &c);
    double v = ph ? (pj ? c : s) : (pj ? -s : c);
    return tf32r((float)v);
}

// ---------------- twiddle/matrix init (double-precision trig) --------------
__global__ void k_init() {
    int i = blockIdx.x * blockDim.x + threadIdx.x;
    if (i >= 16896) return;
    if (i < 33 * 8 * 32) {  // g_fwf : fragment-ordered W-DFT B matrix, tf32
        int kt = i >> 8, rem = i & 255;
        int nt = rem >> 5, lane = rem & 31;
        int c = lane & 3, r = lane >> 2;
        int n = nt * 8 + r, kx = n >> 1, p = n & 1;
        float2 v;
#pragma unroll
        for (int half = 0; half < 2; ++half) {
            int w = kt * 8 + c + 4 * half;
            long m = ((long)w * (long)kx) % WP;
            double ang = TWO_PI_D * (double)m / (double)WP;
            double s, cs; sincos(ang, &s, &cs);
            float val = p ? (float)(-s) : (float)cs;
            if (half == 0) v.x = tf32r(val); else v.y = tf32r(val);
        }
        g_fwf[i] = v;
    }
    if (i < 8 * 33 * 32 + 32) {  // g_awf : fragment-ordered inverse-W, tf32
        float2 v = make_float2(0.f, 0.f);
        if (i < 8448) {
            int ktl = i / 1056, rem = i - ktl * 1056;
            int nt = rem >> 5, lane = rem & 31;
            int cc = lane & 3, rr = lane >> 2;
            int w = nt * 8 + rr;
#pragma unroll
            for (int half = 0; half < 2; ++half) {
                int kk = ktl * 8 + cc + 4 * half;
                int k = kk >> 1;
                double sc = ((k == 0) ? 1.0 : 2.0) / ((double)HP * (double)WP);
                long m = ((long)k * (long)w) % WP;
                double ang = TWO_PI_D * (double)m / (double)WP;
                double s, c; sincos(ang, &s, &c);
                float val = (float)((kk & 1) ? (-sc * s) : (sc * c));
                if (half == 0) v.x = tf32r(val); else v.y = tf32r(val);
            }
        }
        g_awf[i] = v;
    }
    {   // g_fhf : [mt 0..7][kt 0..65][lane]
        int mt = i / 2112, rem = i - mt * 2112;
        int kt = rem >> 5, lane = rem & 31;
        int r = lane >> 2, c = lane & 3;
        float4 v;
        v.x = afh_val(mt * 16 + r,     kt * 8 + c);
        v.y = afh_val(mt * 16 + 8 + r, kt * 8 + c);
        v.z = afh_val(mt * 16 + r,     kt * 8 + c + 4);
        v.w = afh_val(mt * 16 + 8 + r, kt * 8 + c + 4);
        g_fhf[i] = v;
    }
    {   // g_ghf : [mt 0..32][kt 0..15][lane]
        int mt = i / 512, rem = i & 511;
        int kt = rem >> 5, lane = rem & 31;
        int r = lane >> 2, c = lane & 3;
        float4 v;
        v.x = agh_val(mt * 16 + r,     kt * 8 + c);
        v.y = agh_val(mt * 16 + 8 + r, kt * 8 + c);
        v.z = agh_val(mt * 16 + r,     kt * 8 + c + 4);
        v.w = agh_val(mt * 16 + 8 + r, kt * 8 + c + 4);
        g_ghf[i] = v;
    }
}

// Zero only the pad region of g_h[0] (rows >= H0, and cols >= W0 of rows < H0)
__global__ void k_zero_pad() {
    float* p = g_h[0] + (size_t)blockIdx.x * HW;
    int t = threadIdx.x;
    for (int i = t; i < 8 * WP; i += 256)
        p[(H0 + i / WP) * WP + (i % WP)] = 0.f;
    for (int i = t; i < 8 * H0; i += 256)
        p[(i >> 3) * WP + W0 + (i & 7)] = 0.f;
}

// ---------------- lift: [x, gx, gy] -> gelu(W1.) -> W2. -------------------
__global__ void k_lift(const float* __restrict__ x,
                       const float* __restrict__ w1, const float* __restrict__ b1,
                       const float* __restrict__ w2, const float* __restrict__ b2) {
    __shared__ float sw1[160], sb1[32], sw2[2048], sb2[64];
    int t = threadIdx.x;
    if (t < 160) sw1[t] = w1[t];
    if (t < 32)  sb1[t] = b1[t];
    for (int i = t; i < 2048; i += 256) sw2[i] = w2[i];
    if (t < 64)  sb2[t] = b2[t];
    __syncthreads();
    int b = blockIdx.x >> 8, h = blockIdx.x & 255, w = t;
    float in5[5];
#pragma unroll
    for (int c = 0; c < 3; ++c)
        in5[c] = x[(((size_t)b * 3 + c) * H0 + h) * W0 + w];
    in5[3] = (float)h * (1.0f / 255.0f);
    in5[4] = (float)w * (1.0f / 255.0f);
    float mid[32];
#pragma unroll
    for (int o = 0; o < 32; ++o) {
        float s = sb1[o];
#pragma unroll
        for (int i = 0; i < 5; ++i) s = fmaf(sw1[o * 5 + i], in5[i], s);
        mid[o] = gelu_f(s);
    }
    float* hb = g_h[0];
#pragma unroll 4
    for (int o = 0; o < 64; ++o) {
        float s = sb2[o];
#pragma unroll
        for (int i = 0; i < 32; ++i) s = fmaf(sw2[o * 32 + i], mid[i], s);
        hb[(((size_t)b * CW + o) * HP + h) * WP + w] = s;
    }
}

// ---------------- K1: partial rDFT along W via tf32 mma --------------------
__global__ __launch_bounds__(256, 2) void k1_wdft(int cur) {
    extern __shared__ float sA[];                        // [64][268] 68608 B
    const float* hb = g_h[cur] + (size_t)blockIdx.x * 64 * WP;
    for (int idx = threadIdx.x; idx < 64 * 66; idx += 256) {
        int i = idx / 66, cq = idx - i * 66;
        float4 v = *reinterpret_cast<const float4*>(hb + (size_t)i * WP + cq * 4);
        v.x = tf32r(v.x); v.y = tf32r(v.y); v.z = tf32r(v.z); v.w = tf32r(v.w);
        *reinterpret_cast<float4*>(&sA[i * 268 + cq * 4]) = v;
    }
    __syncthreads();
    int lane = threadIdx.x & 31, wid = threadIdx.x >> 5;
    int mi = wid & 3, nh = wid >> 2;
    int m0 = mi * 16;
    int c = lane & 3, r = lane >> 2;
    float acc[4][4];
#pragma unroll
    for (int j = 0; j < 4; ++j) {
        acc[j][0] = 0.f; acc[j][1] = 0.f; acc[j][2] = 0.f; acc[j][3] = 0.f;
    }
    int aRowBase = (m0 + r) * 268 + c;
#pragma unroll 3
    for (int kt = 0; kt < 33; ++kt) {
        int k0 = kt * 8;
        unsigned a0 = __float_as_uint(sA[aRowBase + k0]);
        unsigned a1 = __float_as_uint(sA[aRowBase + 8 * 268 + k0]);
        unsigned a2 = __float_as_uint(sA[aRowBase + k0 + 4]);
        unsigned a3 = __float_as_uint(sA[aRowBase + 8 * 268 + k0 + 4]);
        const float2* bp = &g_fwf[((kt * 8) + nh * 4) * 32 + lane];
#pragma unroll
        for (int j = 0; j < 4; ++j) {
            float2 bb = __ldg(&bp[j * 32]);
            mma_tf32(acc[j], a0, a1, a2, a3,
                     __float_as_uint(bb.x), __float_as_uint(bb.y));
        }
    }
    size_t row0 = (size_t)blockIdx.x * 64 + m0 + r;
#pragma unroll
    for (int j = 0; j < 4; ++j) {
        int kx = (nh * 4 + j) * 4 + c;
        g_x1[row0 * MW + kx]       = make_float2(acc[j][0], acc[j][1]);
        g_x1[(row0 + 8) * MW + kx] = make_float2(acc[j][2], acc[j][3]);
    }
}

// ---------------- K2: partial DFT along H via tf32 mma ---------------------
// per (b,c): C[128 j'][32 kx] = A[128][528] x B[528][32]; A const (g_fhf)
__global__ __launch_bounds__(256, 2) void k2_hdft() {
    extern __shared__ float sB[];                        // [528][40] 84480 B
    int bc = blockIdx.x;
    int t = threadIdx.x;
    const float2* xp = g_x1 + (size_t)bc * HP * MW;
    for (int idx = t; idx < HP * MW; idx += 256) {
        int h = idx >> 5, kx = idx & 31;
        float2 v = xp[idx];
        sB[(2 * h) * 40 + kx]     = tf32r(v.x);
        sB[(2 * h + 1) * 40 + kx] = tf32r(v.y);
    }
    __syncthreads();
    int lane = t & 31, wid = t >> 5;
    int c = lane & 3, r = lane >> 2;
    float acc[4][4];
#pragma unroll
    for (int nt = 0; nt < 4; ++nt) {
        acc[nt][0] = 0.f; acc[nt][1] = 0.f; acc[nt][2] = 0.f; acc[nt][3] = 0.f;
    }
#pragma unroll 2
    for (int kt = 0; kt < 66; ++kt) {
        float4 fa = __ldg(&g_fhf[(wid * 66 + kt) * 32 + lane]);
        unsigned a0 = __float_as_uint(fa.x), a1 = __float_as_uint(fa.y);
        unsigned a2 = __float_as_uint(fa.z), a3 = __float_as_uint(fa.w);
        int bRow0 = (kt * 8 + c) * 40 + r;
        int bRow1 = (kt * 8 + c + 4) * 40 + r;
#pragma unroll
        for (int nt = 0; nt < 4; ++nt) {
            unsigned b0 = __float_as_uint(sB[bRow0 + nt * 8]);
            unsigned b1 = __float_as_uint(sB[bRow1 + nt * 8]);
            mma_tf32(acc[nt], a0, a1, a2, a3, b0, b1);
        }
    }
    int row0 = wid * 16 + r, row1 = row0 + 8;
#pragma unroll
    for (int nt = 0; nt < 4; ++nt) {
        int kxa = nt * 8 + 2 * c;
        *reinterpret_cast<float2*>(&g_x2r[((size_t)bc * 128 + row0) * 32 + kxa]) =
            make_float2(acc[nt][0], acc[nt][1]);
        *reinterpret_cast<float2*>(&g_x2r[((size_t)bc * 128 + row1) * 32 + kxa]) =
            make_float2(acc[nt][2], acc[nt][3]);
    }
}

// ---------------- K3: per-mode channel mixing (x2 -> y2) -------------------
__global__ __launch_bounds__(256) void k3_mix(const float* __restrict__ spw1,
                                              const float* __restrict__ spw2, int l) {
    __shared__ float2 sX[2 * 64 * 32];                   // [b2][i][kx] 32 KB
    int jj = blockIdx.x >> 2, bp = blockIdx.x & 3;
    int b0 = bp * 2;
    int t = threadIdx.x, kx = t & 31, sub = t >> 5;
    for (int idx = t; idx < 4096; idx += 256) {
        int bi = idx >> 11, rest = idx & 2047;
        int i = rest >> 5, kxl = rest & 31;
        const float* pp = g_x2r + ((size_t)((b0 + bi) * CW + i) * 128 + 2 * jj) * 32;
        sX[idx] = make_float2(pp[kxl], pp[32 + kxl]);
    }
    __syncthreads();
    const float2* wp; int jx;
    if (jj < 32) { wp = (const float2*)spw1; jx = jj; }
    else         { wp = (const float2*)spw2; jx = jj - 32; }
    size_t wbase = (size_t)l * 4194304 + (size_t)jx * 32 + kx;
    float2 a0[8], a1[8];
#pragma unroll
    for (int q = 0; q < 8; ++q) { a0[q] = make_float2(0.f, 0.f); a1[q] = make_float2(0.f, 0.f); }
#pragma unroll 2
    for (int i = 0; i < 64; ++i) {
        float2 x0 = sX[i * 32 + kx];
        float2 x1 = sX[2048 + i * 32 + kx];
        size_t row = wbase + (size_t)(i * 64 + sub * 8) * 1024;
#pragma unroll
        for (int q = 0; q < 8; ++q) {
            float2 c = __ldg(&wp[row + (size_t)q * 1024]);
            a0[q].x = fmaf(x0.x, c.x, a0[q].x); a0[q].x = fmaf(-x0.y, c.y, a0[q].x);
            a0[q].y = fmaf(x0.x, c.y, a0[q].y); a0[q].y = fmaf( x0.y, c.x, a0[q].y);
            a1[q].x = fmaf(x1.x, c.x, a1[q].x); a1[q].x = fmaf(-x1.y, c.y, a1[q].x);
            a1[q].y = fmaf(x1.x, c.y, a1[q].y); a1[q].y = fmaf( x1.y, c.x, a1[q].y);
        }
    }
#pragma unroll
    for (int q = 0; q < 8; ++q) {
        int o = sub * 8 + q;
        g_y2[(((size_t)b0       * CW + o) * MH + jj) * MW + kx] = a0[q];
        g_y2[(((size_t)(b0 + 1) * CW + o) * MH + jj) * MW + kx] = a1[q];
    }
}

// ---------------- K4: inverse DFT along H via tf32 mma ---------------------
// per (b,o): C[528 h'][32 kx] = A[528][128] x B[128][32]; A const (g_ghf)
__global__ __launch_bounds__(256) void k4_invh() {
    __shared__ float sB[128 * 40];                       // 20480 B
    int bo = blockIdx.x, b = bo >> 6, o = bo & 63;
    int t = threadIdx.x;
    const float2* yp = g_y2 + (size_t)bo * MH * MW;
    for (int idx = t; idx < MH * MW; idx += 256) {
        int j = idx >> 5, kx = idx & 31;
        float2 v = yp[idx];
        sB[(2 * j) * 40 + kx]     = tf32r(v.x);
        sB[(2 * j + 1) * 40 + kx] = tf32r(v.y);
    }
    __syncthreads();
    int lane = t & 31, wid = t >> 5;
    int c = lane & 3, r = lane >> 2;
    for (int mt = wid; mt < 33; mt += 8) {
        float acc[4][4];
#pragma unroll
        for (int nt = 0; nt < 4; ++nt) {
            acc[nt][0] = 0.f; acc[nt][1] = 0.f; acc[nt][2] = 0.f; acc[nt][3] = 0.f;
        }
#pragma unroll 2
        for (int kt = 0; kt < 16; ++kt) {
            float4 fa = __ldg(&g_ghf[(mt * 16 + kt) * 32 + lane]);
            unsigned a0 = __float_as_uint(fa.x), a1 = __float_as_uint(fa.y);
            unsigned a2 = __float_as_uint(fa.z), a3 = __float_as_uint(fa.w);
            int bRow0 = (kt * 8 + c) * 40 + r;
            int bRow1 = (kt * 8 + c + 4) * 40 + r;
#pragma unroll
            for (int nt = 0; nt < 4; ++nt) {
                unsigned b0 = __float_as_uint(sB[bRow0 + nt * 8]);
                unsigned b1 = __float_as_uint(sB[bRow1 + nt * 8]);
                mma_tf32(acc[nt], a0, a1, a2, a3, b0, b1);
            }
        }
        int h0a = mt * 16 + r, h0b = h0a + 8;
        int ha = h0a >> 1, pa = h0a & 1;
        int hb2 = h0b >> 1, pb = h0b & 1;
        size_t basea = ((size_t)(b * HP + ha) * 64 + o) * 64 + pa;
        size_t baseb = ((size_t)(b * HP + hb2) * 64 + o) * 64 + pb;
#pragma unroll
        for (int nt = 0; nt < 4; ++nt) {
            int kka = 2 * (nt * 8 + 2 * c);
            g_y1n[basea + kka]     = acc[nt][0];
            g_y1n[basea + kka + 2] = acc[nt][1];
            g_y1n[baseb + kka]     = acc[nt][2];
            g_y1n[baseb + kka + 2] = acc[nt][3];
        }
    }
}

// ---------------- K5: tf32 mma GEMM: conv1x1 + inverse-W(c2r) + bias + gelu
__global__ __launch_bounds__(256, 2)
void k5_combine(int cur, const float* __restrict__ cw,
                const float* __restrict__ cb, int l,
                float* __restrict__ out) {
    extern __shared__ float s_raw[];
    float* sAt = s_raw;                 // [o][k] stride 132, 64x132
    float* sB  = s_raw + 64 * 132;      // [k][w] stride 264, 65x264
    int bh = blockIdx.x;
    int b = bh / HP, h = bh - b * HP;
    bool last = (l == NL - 1);
    if (last && h >= H0) return;
    int t = threadIdx.x;
    {
        const float* hb = g_h[cur] + ((size_t)b * CW * HP + h) * WP;
        const size_t rstride = (size_t)HP * WP;
        for (int idx = t; idx < 64 * 66; idx += 256) {
            int i = idx / 66, cq = idx - i * 66;
            float4 v = *reinterpret_cast<const float4*>(hb + (size_t)i * rstride + cq * 4);
            v.x = tf32r(v.x); v.y = tf32r(v.y); v.z = tf32r(v.z); v.w = tf32r(v.w);
            reinterpret_cast<float4*>(sB)[i * 66 + cq] = v;
        }
    }
    {
        const float* cwl = cw + (size_t)l * 4096;
        for (int r2 = t; r2 < 4096; r2 += 256) {
            int o = r2 >> 6, i = r2 & 63;
            sAt[o * 132 + i] = tf32r(cwl[r2]);
        }
        const float* yb = g_y1n + (size_t)(b * HP + h) * 4096;
        for (int r2 = t; r2 < 4096; r2 += 256) {
            int o = r2 >> 6, kk = r2 & 63;
            sAt[o * 132 + 64 + kk] = tf32r(yb[r2]);
        }
    }
    __syncthreads();
    int lane = t & 31, wid = t >> 5;
    int mi = wid & 3, nh = wid >> 2;
    int m0 = mi * 16;
    int c = lane & 3, r = lane >> 2;
    int ntBeg = nh * 17;
    float acc[17][4];
#pragma unroll
    for (int j = 0; j < 17; ++j) {
        acc[j][0] = 0.f; acc[j][1] = 0.f; acc[j][2] = 0.f; acc[j][3] = 0.f;
    }
    int aRowBase = (m0 + r) * 132 + c;
#pragma unroll 2
    for (int kt = 0; kt < 8; ++kt) {
        int k0 = kt * 8;
        unsigned a0 = __float_as_uint(sAt[aRowBase + k0]);
        unsigned a1 = __float_as_uint(sAt[aRowBase + 8 * 132 + k0]);
        unsigned a2 = __float_as_uint(sAt[aRowBase + k0 + 4]);
        unsigned a3 = __float_as_uint(sAt[aRowBase + 8 * 132 + k0 + 4]);
        int bRow = (k0 + c) * 264 + r + ntBeg * 8;
#pragma unroll
        for (int j = 0; j < 17; ++j) {
            unsigned b0 = __float_as_uint(sB[bRow + j * 8]);
            unsigned b1 = __float_as_uint(sB[bRow + 4 * 264 + j * 8]);
            mma_tf32(acc[j], a0, a1, a2, a3, b0, b1);
        }
    }
#pragma unroll 2
    for (int kt = 8; kt < 16; ++kt) {
        int k0 = kt * 8;
        unsigned a0 = __float_as_uint(sAt[aRowBase + k0]);
        unsigned a1 = __float_as_uint(sAt[aRowBase + 8 * 132 + k0]);
        unsigned a2 = __float_as_uint(sAt[aRowBase + k0 + 4]);
        unsigned a3 = __float_as_uint(sAt[aRowBase + 8 * 132 + k0 + 4]);
        const float2* bp = &g_awf[(((kt - 8) * 33) + ntBeg) * 32 + lane];
#pragma unroll
        for (int j = 0; j < 17; ++j) {
            float2 bb = __ldg(&bp[j * 32]);
            mma_tf32(acc[j], a0, a1, a2, a3,
                     __float_as_uint(bb.x), __float_as_uint(bb.y));
        }
    }
    int o0 = m0 + r, o1 = o0 + 8;
    float bias0 = __ldg(&cb[l * 64 + o0]);
    float bias1 = __ldg(&cb[l * 64 + o1]);
    float* hn = g_h[cur ^ 1];
#pragma unroll
    for (int j = 0; j < 17; ++j) {
        if (nh && j == 16) continue;
        int n0 = (ntBeg + j) * 8;
        int wcol = n0 + 2 * c;
        float2 p0 = make_float2(acc[j][0] + bias0, acc[j][1] + bias0);
        float2 p1 = make_float2(acc[j][2] + bias1, acc[j][3] + bias1);
        if (!last) {
            p0.x = gelu_f(p0.x); p0.y = gelu_f(p0.y);
            p1.x = gelu_f(p1.x); p1.y = gelu_f(p1.y);
            *reinterpret_cast<float2*>(
                &hn[(((size_t)b * CW + o0) * HP + h) * WP + wcol]) = p0;
            *reinterpret_cast<float2*>(
                &hn[(((size_t)b * CW + o1) * HP + h) * WP + wcol]) = p1;
        } else if (n0 < W0) {
            *reinterpret_cast<float2*>(
                &out[(((size_t)b * CW + o0) * H0 + h) * W0 + wcol]) = p0;
            *reinterpret_cast<float2*>(
                &out[(((size_t)b * CW + o1) * H0 + h) * W0 + wcol]) = p1;
        }
    }
}

// ---------------- launch ---------------------------------------------------
extern "C" void kernel_launch(void* const* d_in, const int* in_sizes, int n_in,
                              void* d_out, int out_size) {
    const float* x   = (const float*)d_in[0];
    const float* lw1 = (const float*)d_in[1];
    const float* lb1 = (const float*)d_in[2];
    const float* lw2 = (const float*)d_in[3];
    const float* lb2 = (const float*)d_in[4];
    const float* cw  = (const float*)d_in[5];
    const float* cb  = (const float*)d_in[6];
    const float* sp1 = (const float*)d_in[7];
    const float* sp2 = (const float*)d_in[8];
    float* out = (float*)d_out;

    const int SMEM_K1 = 64 * 268 * 4;                      // 68608
    const int SMEM_K2 = 528 * 40 * 4;                      // 84480
    const int SMEM_K5 = (64 * 132 + 65 * 264) * 4;         // 102432

    cudaFuncSetAttribute(k1_wdft,    cudaFuncAttributeMaxDynamicSharedMemorySize, SMEM_K1);
    cudaFuncSetAttribute(k2_hdft,    cudaFuncAttributeMaxDynamicSharedMemorySize, SMEM_K2);
    cudaFuncSetAttribute(k5_combine, cudaFuncAttributeMaxDynamicSharedMemorySize, SMEM_K5);

    k_init<<<66, 256>>>();
    k_zero_pad<<<BATCH * CW, 256>>>();
    k_lift<<<BATCH * 256, 256>>>(x, lw1, lb1, lw2, lb2);

    for (int l = 0; l < NL; ++l) {
        int cur = l & 1;
        k1_wdft<<<(BATCH * CW * HP) / 64, 256, SMEM_K1>>>(cur);
        k2_hdft<<<BATCH * CW, 256, SMEM_K2>>>();
        k3_mix<<<MH * 4, 256>>>(sp1, sp2, l);
        k4_invh<<<BATCH * CW, 256>>>();
        k5_combine<<<BATCH * HP, 256, SMEM_K5>>>(cur, cw, cb, l, out);
    }
}

// round 9
// speedup vs baseline: 4.6122x; 1.3531x over previous
#include <cuda_runtime.h>
#include <cuda_fp16.h>
#include <math.h>

#define BATCH 8
#define CW    64
#define H0    256
#define W0    256
#define HP    264
#define WP    264
#define MW    32      // kept kx modes
#define MH    64      // kept ky modes (32 top + 32 bottom)
#define NL    4
#define HW    (HP*WP)            // 69696
#define NPIX  (BATCH*CW*HW)      // 35684352

// ---------------- scratch (device globals; no allocation allowed) ----------
__device__ __align__(128) float  g_h[2][NPIX];              // 2 x 142.7 MB
__device__ __align__(128) float2 g_x1[BATCH*CW*HP*MW];      // 34.6 MB
__device__ __align__(128) float  g_x2r[BATCH*CW*128*32];    // 8.4 MB (split re/im rows)
__device__ __align__(128) float2 g_y2[BATCH*CW*MH*MW];      // 8.4 MB
__device__ __align__(128) float  g_y1n[BATCH*HP*64*64];     // 34.6 MB [b][h][o][kk]
// fp16 fragment tables (k16)
__device__ __align__(128) uint2 g_fwfh[17*8*32];            // W-DFT B frags
__device__ __align__(128) uint2 g_awfh[4*34*32];            // c2r invW B frags
__device__ __align__(128) uint4 g_fhfh[8*33*32];            // H-DFT A frags
__device__ __align__(128) uint4 g_ghfh[33*8*32];            // invH A frags

__device__ __forceinline__ float gelu_f(float v) {
    return 0.5f * v * (1.0f + erff(v * 0.70710678118654752f));
}

__device__ __forceinline__ unsigned packh(float a, float b) {
    __half2 h = __halves2half2(__float2half_rn(a), __float2half_rn(b));
    return *reinterpret_cast<unsigned*>(&h);
}

// mma.m16n8k16 fp16 in, fp32 accum
__device__ __forceinline__ void mma_f16(float* d, unsigned a0, unsigned a1,
                                        unsigned a2, unsigned a3,
                                        unsigned b0, unsigned b1) {
    asm("mma.sync.aligned.m16n8k16.row.col.f32.f16.f16.f32 "
        "{%0,%1,%2,%3}, {%4,%5,%6,%7}, {%8,%9}, {%0,%1,%2,%3};"
        : "+f"(d[0]), "+f"(d[1]), "+f"(d[2]), "+f"(d[3])
        : "r"(a0), "r"(a1), "r"(a2), "r"(a3), "r"(b0), "r"(b1));
}

#define TWO_PI_D 6.283185307179586476925286766559

// W-DFT B value: col n (2kx+p), row w
__device__ float fwB_val(int n, int w) {
    if (w >= WP) return 0.f;
    int kx = n >> 1, p = n & 1;
    long m = ((long)w * (long)kx) % WP;
    double ang = TWO_PI_D * (double)m / (double)WP;
    double s, c; sincos(ang, &s, &c);
    return p ? (float)(-s) : (float)c;
}
// c2r inverse-W value: row kk, col w
__device__ float awB_val(int kk, int w) {
    if (w >= WP) return 0.f;
    int k = kk >> 1;
    double sc = ((k == 0) ? 1.0 : 2.0) / ((double)HP * (double)WP);
    long m = ((long)k * (long)w) % WP;
    double ang = TWO_PI_D * (double)m / (double)WP;
    double s, c; sincos(ang, &s, &c);
    return (float)((kk & 1) ? (-sc * s) : (sc * c));
}
// H-DFT A: rows j' (2j+pj), cols k' (2h+ph)
__device__ float fh_val(int jp, int kp) {
    int j = jp >> 1, pj = jp & 1, h = kp >> 1, ph = kp & 1;
    int ky = (j < 32) ? j : j + (HP - MH);
    long m = ((long)h * (long)ky) % HP;
    double ang = TWO_PI_D * (double)m / (double)HP;
    double s, c; sincos(ang, &s, &c);
    double v = pj ? (ph ? c : -s) : (ph ? s : c);
    return (float)v;
}
// inverse-H A: rows h' (2h+ph), cols j' (2j+pj)
__device__ float gh_val(int hpp, int jp) {
    int h = hpp >> 1, ph = hpp & 1, j = jp >> 1, pj = jp & 1;
    int ky = (j < 32) ? j : j + (HP - MH);
    long m = ((long)h * (long)ky) % HP;
    double ang = TWO_PI_D * (double)m / (double)HP;
    double s, c; sincos(ang, &s, &c);
    double v = ph ? (pj ? c : s) : (pj ? -s : c);
    return (float)v;
}

// ---------------- fragment-table init --------------------------------------
__global__ void k_init() {
    int i = blockIdx.x * blockDim.x + threadIdx.x;
    if (i >= 16896) return;
    if (i < 17 * 8 * 32) {   // g_fwfh [kt][nt][lane]
        int kt = i >> 8, rem = i & 255;
        int nt = rem >> 5, lane = rem & 31;
        int r = lane >> 2, c = lane & 3;
        int n = nt * 8 + r;
        int w0 = kt * 16 + 2 * c;
        g_fwfh[i] = make_uint2(packh(fwB_val(n, w0),     fwB_val(n, w0 + 1)),
                               packh(fwB_val(n, w0 + 8), fwB_val(n, w0 + 9)));
    }
    if (i < 4 * 34 * 32) {   // g_awfh [kt][ntg][lane]
        int kt = i / (34 * 32), rem = i - kt * (34 * 32);
        int ntg = rem >> 5, lane = rem & 31;
        int r = lane >> 2, c = lane & 3;
        int w = ntg * 8 + r;
        int kk0 = kt * 16 + 2 * c;
        g_awfh[i] = make_uint2(packh(awB_val(kk0, w),     awB_val(kk0 + 1, w)),
                               packh(awB_val(kk0 + 8, w), awB_val(kk0 + 9, w)));
    }
    {   // g_fhfh [mt 0..7][kt 0..32][lane]
        int mt = i / (33 * 32);
        if (mt < 8) {
            int rem = i - mt * 33 * 32;
            int kt = rem >> 5, lane = rem & 31;
            int r = lane >> 2, c = lane & 3;
            int row0 = mt * 16 + r, k0 = kt * 16 + 2 * c;
            g_fhfh[i] = make_uint4(
                packh(fh_val(row0, k0),         fh_val(row0, k0 + 1)),
                packh(fh_val(row0 + 8, k0),     fh_val(row0 + 8, k0 + 1)),
                packh(fh_val(row0, k0 + 8),     fh_val(row0, k0 + 9)),
                packh(fh_val(row0 + 8, k0 + 8), fh_val(row0 + 8, k0 + 9)));
        }
    }
    {   // g_ghfh [mt 0..32][kt 0..7][lane]
        int mt = i >> 8;
        if (mt < 33) {
            int rem = i & 255;
            int kt = rem >> 5, lane = rem & 31;
            int r = lane >> 2, c = lane & 3;
            int row0 = mt * 16 + r, k0 = kt * 16 + 2 * c;
            g_ghfh[i] = make_uint4(
                packh(gh_val(row0, k0),         gh_val(row0, k0 + 1)),
                packh(gh_val(row0 + 8, k0),     gh_val(row0 + 8, k0 + 1)),
                packh(gh_val(row0, k0 + 8),     gh_val(row0, k0 + 9)),
                packh(gh_val(row0 + 8, k0 + 8), gh_val(row0 + 8, k0 + 9)));
        }
    }
}

// Zero only the pad region of g_h[0]
__global__ void k_zero_pad() {
    float* p = g_h[0] + (size_t)blockIdx.x * HW;
    int t = threadIdx.x;
    for (int i = t; i < 8 * WP; i += 256)
        p[(H0 + i / WP) * WP + (i % WP)] = 0.f;
    for (int i = t; i < 8 * H0; i += 256)
        p[(i >> 3) * WP + W0 + (i & 7)] = 0.f;
}

// ---------------- lift ------------------------------------------------------
__global__ void k_lift(const float* __restrict__ x,
                       const float* __restrict__ w1, const float* __restrict__ b1,
                       const float* __restrict__ w2, const float* __restrict__ b2) {
    __shared__ float sw1[160], sb1[32], sw2[2048], sb2[64];
    int t = threadIdx.x;
    if (t < 160) sw1[t] = w1[t];
    if (t < 32)  sb1[t] = b1[t];
    for (int i = t; i < 2048; i += 256) sw2[i] = w2[i];
    if (t < 64)  sb2[t] = b2[t];
    __syncthreads();
    int b = blockIdx.x >> 8, h = blockIdx.x & 255, w = t;
    float in5[5];
#pragma unroll
    for (int c = 0; c < 3; ++c)
        in5[c] = x[(((size_t)b * 3 + c) * H0 + h) * W0 + w];
    in5[3] = (float)h * (1.0f / 255.0f);
    in5[4] = (float)w * (1.0f / 255.0f);
    float mid[32];
#pragma unroll
    for (int o = 0; o < 32; ++o) {
        float s = sb1[o];
#pragma unroll
        for (int i = 0; i < 5; ++i) s = fmaf(sw1[o * 5 + i], in5[i], s);
        mid[o] = gelu_f(s);
    }
    float* hb = g_h[0];
#pragma unroll 4
    for (int o = 0; o < 64; ++o) {
        float s = sb2[o];
#pragma unroll
        for (int i = 0; i < 32; ++i) s = fmaf(sw2[o * 32 + i], mid[i], s);
        hb[(((size_t)b * CW + o) * HP + h) * WP + w] = s;
    }
}

// ---------------- K1: W-DFT via fp16 mma -----------------------------------
// C[64 rows][64 n] = A[64][264] x B[264][64]; B const (g_fwfh)
__global__ __launch_bounds__(256, 3) void k1_wdft(int cur) {
    extern __shared__ unsigned sAw[];                    // (64*132 + 8) words
    __half* sAh = reinterpret_cast<__half*>(sAw);
    const float* hb = g_h[cur] + (size_t)blockIdx.x * 64 * WP;
    for (int idx = threadIdx.x; idx < 64 * 66; idx += 256) {
        int row = idx / 66, cq = idx - row * 66;
        float4 v = *reinterpret_cast<const float4*>(hb + (size_t)row * WP + cq * 4);
        sAw[row * 132 + cq * 2]     = packh(v.x, v.y);
        sAw[row * 132 + cq * 2 + 1] = packh(v.z, v.w);
    }
    if (threadIdx.x < 8) sAw[64 * 132 + threadIdx.x] = 0u;
    __syncthreads();
    int lane = threadIdx.x & 31, wid = threadIdx.x >> 5;
    int mi = wid & 3, nh = wid >> 2;
    int m0 = mi * 16;
    int c = lane & 3, r = lane >> 2;
    float acc[4][4];
#pragma unroll
    for (int j = 0; j < 4; ++j) {
        acc[j][0] = 0.f; acc[j][1] = 0.f; acc[j][2] = 0.f; acc[j][3] = 0.f;
    }
    int aw0 = (m0 + r) * 132 + c;
    int aw1 = aw0 + 8 * 132;
#pragma unroll 4
    for (int kt = 0; kt < 17; ++kt) {
        unsigned a0 = sAw[aw0 + kt * 8];
        unsigned a1 = sAw[aw1 + kt * 8];
        unsigned a2 = sAw[aw0 + kt * 8 + 4];
        unsigned a3 = sAw[aw1 + kt * 8 + 4];
        const uint2* bp = &g_fwfh[(kt * 8 + nh * 4) * 32 + lane];
#pragma unroll
        for (int j = 0; j < 4; ++j) {
            uint2 bb = __ldg(&bp[j * 32]);
            mma_f16(acc[j], a0, a1, a2, a3, bb.x, bb.y);
        }
    }
    size_t row0 = (size_t)blockIdx.x * 64 + m0 + r;
#pragma unroll
    for (int j = 0; j < 4; ++j) {
        int kx = (nh * 4 + j) * 4 + c;
        g_x1[row0 * MW + kx]       = make_float2(acc[j][0], acc[j][1]);
        g_x1[(row0 + 8) * MW + kx] = make_float2(acc[j][2], acc[j][3]);
    }
}

// ---------------- K2: H-DFT via fp16 mma -----------------------------------
// per (b,c): C[128 j'][32 kx] = A[128][528] x B[528][32]; A const (g_fhfh)
__global__ __launch_bounds__(256, 3) void k2_hdft() {
    extern __shared__ unsigned sBw[];                    // 264*40 words
    int bc = blockIdx.x;
    int t = threadIdx.x;
    const float2* xp = g_x1 + (size_t)bc * HP * MW;
    for (int idx = t; idx < HP * MW; idx += 256) {
        int h = idx >> 5, kx = idx & 31;
        float2 v = xp[idx];
        sBw[h * 40 + kx] = packh(v.x, v.y);              // k pair (2h re, 2h+1 im)
    }
    __syncthreads();
    int lane = t & 31, wid = t >> 5;                     // wid = mt
    int c = lane & 3, r = lane >> 2;
    float acc[4][4];
#pragma unroll
    for (int nt = 0; nt < 4; ++nt) {
        acc[nt][0] = 0.f; acc[nt][1] = 0.f; acc[nt][2] = 0.f; acc[nt][3] = 0.f;
    }
#pragma unroll 3
    for (int kt = 0; kt < 33; ++kt) {
        uint4 fa = __ldg(&g_fhfh[(wid * 33 + kt) * 32 + lane]);
        int bw = (kt * 8 + c) * 40 + r;
#pragma unroll
        for (int nt = 0; nt < 4; ++nt) {
            unsigned b0 = sBw[bw + nt * 8];
            unsigned b1 = sBw[bw + 4 * 40 + nt * 8];
            mma_f16(acc[nt], fa.x, fa.y, fa.z, fa.w, b0, b1);
        }
    }
    int row0 = wid * 16 + r, row1 = row0 + 8;
#pragma unroll
    for (int nt = 0; nt < 4; ++nt) {
        int kxa = nt * 8 + 2 * c;
        *reinterpret_cast<float2*>(&g_x2r[((size_t)bc * 128 + row0) * 32 + kxa]) =
            make_float2(acc[nt][0], acc[nt][1]);
        *reinterpret_cast<float2*>(&g_x2r[((size_t)bc * 128 + row1) * 32 + kxa]) =
            make_float2(acc[nt][2], acc[nt][3]);
    }
}

// ---------------- K3: per-mode channel mixing (x2 -> y2) -------------------
__global__ __launch_bounds__(256) void k3_mix(const float* __restrict__ spw1,
                                              const float* __restrict__ spw2, int l) {
    __shared__ float2 sX[2 * 64 * 32];                   // [b2][i][kx] 32 KB
    int jj = blockIdx.x >> 2, bp = blockIdx.x & 3;
    int b0 = bp * 2;
    int t = threadIdx.x, kx = t & 31, sub = t >> 5;
    for (int idx = t; idx < 4096; idx += 256) {
        int bi = idx >> 11, rest = idx & 2047;
        int i = rest >> 5, kxl = rest & 31;
        const float* pp = g_x2r + ((size_t)((b0 + bi) * CW + i) * 128 + 2 * jj) * 32;
        sX[idx] = make_float2(pp[kxl], pp[32 + kxl]);
    }
    __syncthreads();
    const float2* wp; int jx;
    if (jj < 32) { wp = (const float2*)spw1; jx = jj; }
    else         { wp = (const float2*)spw2; jx = jj - 32; }
    size_t wbase = (size_t)l * 4194304 + (size_t)jx * 32 + kx;
    float2 a0[8], a1[8];
#pragma unroll
    for (int q = 0; q < 8; ++q) { a0[q] = make_float2(0.f, 0.f); a1[q] = make_float2(0.f, 0.f); }
#pragma unroll 2
    for (int i = 0; i < 64; ++i) {
        float2 x0 = sX[i * 32 + kx];
        float2 x1 = sX[2048 + i * 32 + kx];
        size_t row = wbase + (size_t)(i * 64 + sub * 8) * 1024;
#pragma unroll
        for (int q = 0; q < 8; ++q) {
            float2 c = __ldg(&wp[row + (size_t)q * 1024]);
            a0[q].x = fmaf(x0.x, c.x, a0[q].x); a0[q].x = fmaf(-x0.y, c.y, a0[q].x);
            a0[q].y = fmaf(x0.x, c.y, a0[q].y); a0[q].y = fmaf( x0.y, c.x, a0[q].y);
            a1[q].x = fmaf(x1.x, c.x, a1[q].x); a1[q].x = fmaf(-x1.y, c.y, a1[q].x);
            a1[q].y = fmaf(x1.x, c.y, a1[q].y); a1[q].y = fmaf( x1.y, c.x, a1[q].y);
        }
    }
#pragma unroll
    for (int q = 0; q < 8; ++q) {
        int o = sub * 8 + q;
        g_y2[(((size_t)b0       * CW + o) * MH + jj) * MW + kx] = a0[q];
        g_y2[(((size_t)(b0 + 1) * CW + o) * MH + jj) * MW + kx] = a1[q];
    }
}

// ---------------- K4: inverse H-DFT via fp16 mma ---------------------------
// per (b,o): C[528 h'][32 kx] = A[528][128] x B[128][32]; A const (g_ghfh)
__global__ __launch_bounds__(256) void k4_invh() {
    __shared__ unsigned sBw[64 * 40];
    int bo = blockIdx.x, b = bo >> 6, o = bo & 63;
    int t = threadIdx.x;
    const float2* yp = g_y2 + (size_t)bo * MH * MW;
    for (int idx = t; idx < MH * MW; idx += 256) {
        int j = idx >> 5, kx = idx & 31;
        float2 v = yp[idx];
        sBw[j * 40 + kx] = packh(v.x, v.y);
    }
    __syncthreads();
    int lane = t & 31, wid = t >> 5;
    int c = lane & 3, r = lane >> 2;
    for (int mt = wid; mt < 33; mt += 8) {
        float acc[4][4];
#pragma unroll
        for (int nt = 0; nt < 4; ++nt) {
            acc[nt][0] = 0.f; acc[nt][1] = 0.f; acc[nt][2] = 0.f; acc[nt][3] = 0.f;
        }
#pragma unroll
        for (int kt = 0; kt < 8; ++kt) {
            uint4 fa = __ldg(&g_ghfh[(mt * 8 + kt) * 32 + lane]);
            int bw = (kt * 8 + c) * 40 + r;
#pragma unroll
            for (int nt = 0; nt < 4; ++nt) {
                unsigned b0 = sBw[bw + nt * 8];
                unsigned b1 = sBw[bw + 4 * 40 + nt * 8];
                mma_f16(acc[nt], fa.x, fa.y, fa.z, fa.w, b0, b1);
            }
        }
        int h0a = mt * 16 + r, h0b = h0a + 8;
        int ha = h0a >> 1, pa = h0a & 1;
        int hb2 = h0b >> 1, pb = h0b & 1;
        size_t basea = ((size_t)(b * HP + ha) * 64 + o) * 64 + pa;
        size_t baseb = ((size_t)(b * HP + hb2) * 64 + o) * 64 + pb;
#pragma unroll
        for (int nt = 0; nt < 4; ++nt) {
            int kka = 2 * (nt * 8 + 2 * c);
            g_y1n[basea + kka]     = acc[nt][0];
            g_y1n[basea + kka + 2] = acc[nt][1];
            g_y1n[baseb + kka]     = acc[nt][2];
            g_y1n[baseb + kka + 2] = acc[nt][3];
        }
    }
}

// ---------------- K5: fp16 mma GEMM: conv1x1 + inverse-W(c2r) + bias + gelu
__global__ __launch_bounds__(256, 2)
void k5_combine(int cur, const float* __restrict__ cw,
                const float* __restrict__ cb, int l,
                float* __restrict__ out) {
    extern __shared__ unsigned s_raw_u[];
    unsigned* sAw = s_raw_u;                      // [o][kpair] stride 68 words
    unsigned* sBw = s_raw_u + 64 * 68;            // [kpair][w] stride 264 words (+16 slack)
    int bh = blockIdx.x;
    int b = bh / HP, h = bh - b * HP;
    bool last = (l == NL - 1);
    if (last && h >= H0) return;
    int t = threadIdx.x;
    // stage B (conv half k<64): pair rows (2kp, 2kp+1)
    {
        const float* hb = g_h[cur] + ((size_t)b * CW * HP + h) * WP;
        const size_t rstride = (size_t)HP * WP;
        for (int idx = t; idx < 32 * 66; idx += 256) {
            int kp = idx / 66, cq = idx - kp * 66;
            const float* r0p = hb + (size_t)(2 * kp) * rstride + cq * 4;
            float4 v0 = *reinterpret_cast<const float4*>(r0p);
            float4 v1 = *reinterpret_cast<const float4*>(r0p + rstride);
            int wbase = kp * 264 + cq * 4;
            sBw[wbase]     = packh(v0.x, v1.x);
            sBw[wbase + 1] = packh(v0.y, v1.y);
            sBw[wbase + 2] = packh(v0.z, v1.z);
            sBw[wbase + 3] = packh(v0.w, v1.w);
        }
        if (t < 16) sBw[32 * 264 + t] = 0u;
    }
    // stage A: conv weights + spectral coeffs, half pairs over k
    {
        const float* cwl = cw + (size_t)l * 4096;
        for (int idx = t; idx < 2048; idx += 256) {
            int o = idx >> 5, ip = idx & 31;
            sAw[o * 68 + ip] = packh(cwl[o * 64 + 2 * ip], cwl[o * 64 + 2 * ip + 1]);
        }
        const float* yb = g_y1n + (size_t)(b * HP + h) * 4096;
        for (int idx = t; idx < 2048; idx += 256) {
            int o = idx >> 5, kp = idx & 31;
            sAw[o * 68 + 32 + kp] = packh(yb[o * 64 + 2 * kp], yb[o * 64 + 2 * kp + 1]);
        }
    }
    __syncthreads();
    int lane = t & 31, wid = t >> 5;
    int mi = wid & 3, nh = wid >> 2;
    int m0 = mi * 16;
    int c = lane & 3, r = lane >> 2;
    int ntBeg = nh * 17;
    float acc[17][4];
#pragma unroll
    for (int j = 0; j < 17; ++j) {
        acc[j][0] = 0.f; acc[j][1] = 0.f; acc[j][2] = 0.f; acc[j][3] = 0.f;
    }
    int aw0 = (m0 + r) * 68 + c;
    int aw1 = aw0 + 8 * 68;
    // conv half (kt 0..3): B from smem
#pragma unroll
    for (int kt = 0; kt < 4; ++kt) {
        unsigned a0 = sAw[aw0 + kt * 8];
        unsigned a1 = sAw[aw1 + kt * 8];
        unsigned a2 = sAw[aw0 + kt * 8 + 4];
        unsigned a3 = sAw[aw1 + kt * 8 + 4];
        int bw = (kt * 8 + c) * 264 + r + ntBeg * 8;
#pragma unroll
        for (int j = 0; j < 17; ++j) {
            unsigned b0 = sBw[bw + j * 8];
            unsigned b1 = sBw[bw + 4 * 264 + j * 8];
            mma_f16(acc[j], a0, a1, a2, a3, b0, b1);
        }
    }
    // spectral half (kt 4..7): B frags pre-swizzled in g_awfh
#pragma unroll
    for (int kt = 4; kt < 8; ++kt) {
        unsigned a0 = sAw[aw0 + kt * 8];
        unsigned a1 = sAw[aw1 + kt * 8];
        unsigned a2 = sAw[aw0 + kt * 8 + 4];
        unsigned a3 = sAw[aw1 + kt * 8 + 4];
        const uint2* bp = &g_awfh[((kt - 4) * 34 + ntBeg) * 32 + lane];
#pragma unroll
        for (int j = 0; j < 17; ++j) {
            uint2 bb = __ldg(&bp[j * 32]);
            mma_f16(acc[j], a0, a1, a2, a3, bb.x, bb.y);
        }
    }
    int o0 = m0 + r, o1 = o0 + 8;
    float bias0 = __ldg(&cb[l * 64 + o0]);
    float bias1 = __ldg(&cb[l * 64 + o1]);
    float* hn = g_h[cur ^ 1];
#pragma unroll
    for (int j = 0; j < 17; ++j) {
        if (nh && j == 16) continue;
        int n0 = (ntBeg + j) * 8;
        int wcol = n0 + 2 * c;
        float2 p0 = make_float2(acc[j][0] + bias0, acc[j][1] + bias0);
        float2 p1 = make_float2(acc[j][2] + bias1, acc[j][3] + bias1);
        if (!last) {
            p0.x = gelu_f(p0.x); p0.y = gelu_f(p0.y);
            p1.x = gelu_f(p1.x); p1.y = gelu_f(p1.y);
            *reinterpret_cast<float2*>(
                &hn[(((size_t)b * CW + o0) * HP + h) * WP + wcol]) = p0;
            *reinterpret_cast<float2*>(
                &hn[(((size_t)b * CW + o1) * HP + h) * WP + wcol]) = p1;
        } else if (n0 < W0) {
            *reinterpret_cast<float2*>(
                &out[(((size_t)b * CW + o0) * H0 + h) * W0 + wcol]) = p0;
            *reinterpret_cast<float2*>(
                &out[(((size_t)b * CW + o1) * H0 + h) * W0 + wcol]) = p1;
        }
    }
}

// ---------------- launch ---------------------------------------------------
extern "C" void kernel_launch(void* const* d_in, const int* in_sizes, int n_in,
                              void* d_out, int out_size) {
    const float* x   = (const float*)d_in[0];
    const float* lw1 = (const float*)d_in[1];
    const float* lb1 = (const float*)d_in[2];
    const float* lw2 = (const float*)d_in[3];
    const float* lb2 = (const float*)d_in[4];
    const float* cw  = (const float*)d_in[5];
    const float* cb  = (const float*)d_in[6];
    const float* sp1 = (const float*)d_in[7];
    const float* sp2 = (const float*)d_in[8];
    float* out = (float*)d_out;

    const int SMEM_K1 = (64 * 132 + 8) * 4;                // 33824
    const int SMEM_K2 = 264 * 40 * 4;                      // 42240
    const int SMEM_K5 = (64 * 68 + 32 * 264 + 16) * 4;     // 51264

    cudaFuncSetAttribute(k1_wdft,    cudaFuncAttributeMaxDynamicSharedMemorySize, SMEM_K1);
    cudaFuncSetAttribute(k2_hdft,    cudaFuncAttributeMaxDynamicSharedMemorySize, SMEM_K2);
    cudaFuncSetAttribute(k5_combine, cudaFuncAttributeMaxDynamicSharedMemorySize, SMEM_K5);

    k_init<<<66, 256>>>();
    k_zero_pad<<<BATCH * CW, 256>>>();
    k_lift<<<BATCH * 256, 256>>>(x, lw1, lb1, lw2, lb2);

    for (int l = 0; l < NL; ++l) {
        int cur = l & 1;
        k1_wdft<<<(BATCH * CW * HP) / 64, 256, SMEM_K1>>>(cur);
        k2_hdft<<<BATCH * CW, 256, SMEM_K2>>>();
        k3_mix<<<MH * 4, 256>>>(sp1, sp2, l);
        k4_invh<<<BATCH * CW, 256>>>();
        k5_combine<<<BATCH * HP, 256, SMEM_K5>>>(cur, cw, cb, l, out);
    }
}

// round 10
// speedup vs baseline: 5.1770x; 1.1224x over previous
#include <cuda_runtime.h>
#include <cuda_fp16.h>
#include <math.h>

#define BATCH 8
#define CW    64
#define H0    256
#define W0    256
#define HP    264
#define WP    264
#define MW    32      // kept kx modes
#define MH    64      // kept ky modes (32 top + 32 bottom)
#define NL    4
#define HW    (HP*WP)            // 69696
#define NPIX  (BATCH*CW*HW)      // 35684352

// ---------------- scratch (device globals; no allocation allowed) ----------
__device__ __align__(128) __half   g_hh[2][NPIX];           // 2 x 71.4 MB
__device__ __align__(128) unsigned g_x1h[BATCH*CW*HP*MW];   // 17.3 MB packed (re,im)
__device__ __align__(128) float    g_x2r[BATCH*CW*128*32];  // 8.4 MB (split re/im rows)
__device__ __align__(128) float2   g_y2[BATCH*CW*MH*MW];    // 8.4 MB
__device__ __align__(128) __half   g_y1h[BATCH*HP*64*64];   // 17.3 MB [b][h][o][kk]
// fp16 fragment tables (k16)
__device__ __align__(128) uint2 g_fwfh[17*8*32];            // W-DFT B frags
__device__ __align__(128) uint2 g_awfh[4*34*32];            // c2r invW B frags
__device__ __align__(128) uint4 g_fhfh[8*33*32];            // H-DFT A frags
__device__ __align__(128) uint4 g_ghfh[33*8*32];            // invH A frags

__device__ __forceinline__ float gelu_f(float v) {
    return 0.5f * v * (1.0f + erff(v * 0.70710678118654752f));
}

__device__ __forceinline__ unsigned packh(float a, float b) {
    __half2 h = __halves2half2(__float2half_rn(a), __float2half_rn(b));
    return *reinterpret_cast<unsigned*>(&h);
}

// mma.m16n8k16 fp16 in, fp32 accum
__device__ __forceinline__ void mma_f16(float* d, unsigned a0, unsigned a1,
                                        unsigned a2, unsigned a3,
                                        unsigned b0, unsigned b1) {
    asm("mma.sync.aligned.m16n8k16.row.col.f32.f16.f16.f32 "
        "{%0,%1,%2,%3}, {%4,%5,%6,%7}, {%8,%9}, {%0,%1,%2,%3};"
        : "+f"(d[0]), "+f"(d[1]), "+f"(d[2]), "+f"(d[3])
        : "r"(a0), "r"(a1), "r"(a2), "r"(a3), "r"(b0), "r"(b1));
}

#define TWO_PI_D 6.283185307179586476925286766559

// W-DFT B value: col n (2kx+p), row w
__device__ float fwB_val(int n, int w) {
    if (w >= WP) return 0.f;
    int kx = n >> 1, p = n & 1;
    long m = ((long)w * (long)kx) % WP;
    double ang = TWO_PI_D * (double)m / (double)WP;
    double s, c; sincos(ang, &s, &c);
    return p ? (float)(-s) : (float)c;
}
// c2r inverse-W value: row kk, col w
__device__ float awB_val(int kk, int w) {
    if (w >= WP) return 0.f;
    int k = kk >> 1;
    double sc = ((k == 0) ? 1.0 : 2.0) / ((double)HP * (double)WP);
    long m = ((long)k * (long)w) % WP;
    double ang = TWO_PI_D * (double)m / (double)WP;
    double s, c; sincos(ang, &s, &c);
    return (float)((kk & 1) ? (-sc * s) : (sc * c));
}
// H-DFT A: rows j' (2j+pj), cols k' (2h+ph)
__device__ float fh_val(int jp, int kp) {
    int j = jp >> 1, pj = jp & 1, h = kp >> 1, ph = kp & 1;
    int ky = (j < 32) ? j : j + (HP - MH);
    long m = ((long)h * (long)ky) % HP;
    double ang = TWO_PI_D * (double)m / (double)HP;
    double s, c; sincos(ang, &s, &c);
    double v = pj ? (ph ? c : -s) : (ph ? s : c);
    return (float)v;
}
// inverse-H A: rows h' (2h+ph), cols j' (2j+pj)
__device__ float gh_val(int hpp, int jp) {
    int h = hpp >> 1, ph = hpp & 1, j = jp >> 1, pj = jp & 1;
    int ky = (j < 32) ? j : j + (HP - MH);
    long m = ((long)h * (long)ky) % HP;
    double ang = TWO_PI_D * (double)m / (double)HP;
    double s, c; sincos(ang, &s, &c);
    double v = ph ? (pj ? c : s) : (pj ? -s : c);
    return (float)v;
}

// ---------------- fragment-table init --------------------------------------
__global__ void k_init() {
    int i = blockIdx.x * blockDim.x + threadIdx.x;
    if (i >= 16896) return;
    if (i < 17 * 8 * 32) {   // g_fwfh [kt][nt][lane]
        int kt = i >> 8, rem = i & 255;
        int nt = rem >> 5, lane = rem & 31;
        int r = lane >> 2, c = lane & 3;
        int n = nt * 8 + r;
        int w0 = kt * 16 + 2 * c;
        g_fwfh[i] = make_uint2(packh(fwB_val(n, w0),     fwB_val(n, w0 + 1)),
                               packh(fwB_val(n, w0 + 8), fwB_val(n, w0 + 9)));
    }
    if (i < 4 * 34 * 32) {   // g_awfh [kt][ntg][lane]
        int kt = i / (34 * 32), rem = i - kt * (34 * 32);
        int ntg = rem >> 5, lane = rem & 31;
        int r = lane >> 2, c = lane & 3;
        int w = ntg * 8 + r;
        int kk0 = kt * 16 + 2 * c;
        g_awfh[i] = make_uint2(packh(awB_val(kk0, w),     awB_val(kk0 + 1, w)),
                               packh(awB_val(kk0 + 8, w), awB_val(kk0 + 9, w)));
    }
    {   // g_fhfh [mt 0..7][kt 0..32][lane]
        int mt = i / (33 * 32);
        if (mt < 8) {
            int rem = i - mt * 33 * 32;
            int kt = rem >> 5, lane = rem & 31;
            int r = lane >> 2, c = lane & 3;
            int row0 = mt * 16 + r, k0 = kt * 16 + 2 * c;
            g_fhfh[i] = make_uint4(
                packh(fh_val(row0, k0),         fh_val(row0, k0 + 1)),
                packh(fh_val(row0 + 8, k0),     fh_val(row0 + 8, k0 + 1)),
                packh(fh_val(row0, k0 + 8),     fh_val(row0, k0 + 9)),
                packh(fh_val(row0 + 8, k0 + 8), fh_val(row0 + 8, k0 + 9)));
        }
    }
    {   // g_ghfh [mt 0..32][kt 0..7][lane]
        int mt = i >> 8;
        if (mt < 33) {
            int rem = i & 255;
            int kt = rem >> 5, lane = rem & 31;
            int r = lane >> 2, c = lane & 3;
            int row0 = mt * 16 + r, k0 = kt * 16 + 2 * c;
            g_ghfh[i] = make_uint4(
                packh(gh_val(row0, k0),         gh_val(row0, k0 + 1)),
                packh(gh_val(row0 + 8, k0),     gh_val(row0 + 8, k0 + 1)),
                packh(gh_val(row0, k0 + 8),     gh_val(row0, k0 + 9)),
                packh(gh_val(row0 + 8, k0 + 8), gh_val(row0 + 8, k0 + 9)));
        }
    }
}

// Zero only the pad region of g_hh[0]
__global__ void k_zero_pad() {
    __half* p = g_hh[0] + (size_t)blockIdx.x * HW;
    int t = threadIdx.x;
    __half z = __float2half_rn(0.f);
    for (int i = t; i < 8 * WP; i += 256)
        p[(H0 + i / WP) * WP + (i % WP)] = z;
    for (int i = t; i < 8 * H0; i += 256)
        p[(i >> 3) * WP + W0 + (i & 7)] = z;
}

// ---------------- lift ------------------------------------------------------
__global__ void k_lift(const float* __restrict__ x,
                       const float* __restrict__ w1, const float* __restrict__ b1,
                       const float* __restrict__ w2, const float* __restrict__ b2) {
    __shared__ float sw1[160], sb1[32], sw2[2048], sb2[64];
    int t = threadIdx.x;
    if (t < 160) sw1[t] = w1[t];
    if (t < 32)  sb1[t] = b1[t];
    for (int i = t; i < 2048; i += 256) sw2[i] = w2[i];
    if (t < 64)  sb2[t] = b2[t];
    __syncthreads();
    int b = blockIdx.x >> 8, h = blockIdx.x & 255, w = t;
    float in5[5];
#pragma unroll
    for (int c = 0; c < 3; ++c)
        in5[c] = x[(((size_t)b * 3 + c) * H0 + h) * W0 + w];
    in5[3] = (float)h * (1.0f / 255.0f);
    in5[4] = (float)w * (1.0f / 255.0f);
    float mid[32];
#pragma unroll
    for (int o = 0; o < 32; ++o) {
        float s = sb1[o];
#pragma unroll
        for (int i = 0; i < 5; ++i) s = fmaf(sw1[o * 5 + i], in5[i], s);
        mid[o] = gelu_f(s);
    }
    __half* hb = g_hh[0];
#pragma unroll 4
    for (int o = 0; o < 64; ++o) {
        float s = sb2[o];
#pragma unroll
        for (int i = 0; i < 32; ++i) s = fmaf(sw2[o * 32 + i], mid[i], s);
        hb[(((size_t)b * CW + o) * HP + h) * WP + w] = __float2half_rn(s);
    }
}

// ---------------- K1: W-DFT via fp16 mma -----------------------------------
// C[64 rows][64 n] = A[64][264] x B[264][64]; B const (g_fwfh)
__global__ __launch_bounds__(256, 3) void k1_wdft(int cur) {
    extern __shared__ unsigned sAw[];                    // (64*132 + 8) words
    const uint4* src = reinterpret_cast<const uint4*>(
        g_hh[cur] + (size_t)blockIdx.x * 64 * WP);
    uint4* dst4 = reinterpret_cast<uint4*>(sAw);
    for (int idx = threadIdx.x; idx < 64 * 33; idx += 256)
        dst4[idx] = src[idx];                            // pairs already in k-pair order
    if (threadIdx.x < 8) sAw[64 * 132 + threadIdx.x] = 0u;
    __syncthreads();
    int lane = threadIdx.x & 31, wid = threadIdx.x >> 5;
    int mi = wid & 3, nh = wid >> 2;
    int m0 = mi * 16;
    int c = lane & 3, r = lane >> 2;
    float acc[4][4];
#pragma unroll
    for (int j = 0; j < 4; ++j) {
        acc[j][0] = 0.f; acc[j][1] = 0.f; acc[j][2] = 0.f; acc[j][3] = 0.f;
    }
    int aw0 = (m0 + r) * 132 + c;
    int aw1 = aw0 + 8 * 132;
#pragma unroll 4
    for (int kt = 0; kt < 17; ++kt) {
        unsigned a0 = sAw[aw0 + kt * 8];
        unsigned a1 = sAw[aw1 + kt * 8];
        unsigned a2 = sAw[aw0 + kt * 8 + 4];
        unsigned a3 = sAw[aw1 + kt * 8 + 4];
        const uint2* bp = &g_fwfh[(kt * 8 + nh * 4) * 32 + lane];
#pragma unroll
        for (int j = 0; j < 4; ++j) {
            uint2 bb = __ldg(&bp[j * 32]);
            mma_f16(acc[j], a0, a1, a2, a3, bb.x, bb.y);
        }
    }
    size_t row0 = (size_t)blockIdx.x * 64 + m0 + r;
#pragma unroll
    for (int j = 0; j < 4; ++j) {
        int kx = (nh * 4 + j) * 4 + c;
        g_x1h[row0 * MW + kx]       = packh(acc[j][0], acc[j][1]);
        g_x1h[(row0 + 8) * MW + kx] = packh(acc[j][2], acc[j][3]);
    }
}

// ---------------- K2: H-DFT via fp16 mma -----------------------------------
// per (b,c): C[128 j'][32 kx] = A[128][528] x B[528][32]; A const (g_fhfh)
__global__ __launch_bounds__(256, 3) void k2_hdft() {
    extern __shared__ unsigned sBw[];                    // 264*40 words
    int bc = blockIdx.x;
    int t = threadIdx.x;
    const uint4* xp = reinterpret_cast<const uint4*>(g_x1h + (size_t)bc * HP * MW);
    for (int idx = t; idx < HP * 8; idx += 256) {
        int h = idx >> 3, kq = idx & 7;
        *reinterpret_cast<uint4*>(&sBw[h * 40 + kq * 4]) = xp[idx];
    }
    __syncthreads();
    int lane = t & 31, wid = t >> 5;                     // wid = mt
    int c = lane & 3, r = lane >> 2;
    float acc[4][4];
#pragma unroll
    for (int nt = 0; nt < 4; ++nt) {
        acc[nt][0] = 0.f; acc[nt][1] = 0.f; acc[nt][2] = 0.f; acc[nt][3] = 0.f;
    }
#pragma unroll 3
    for (int kt = 0; kt < 33; ++kt) {
        uint4 fa = __ldg(&g_fhfh[(wid * 33 + kt) * 32 + lane]);
        int bw = (kt * 8 + c) * 40 + r;
#pragma unroll
        for (int nt = 0; nt < 4; ++nt) {
            unsigned b0 = sBw[bw + nt * 8];
            unsigned b1 = sBw[bw + 4 * 40 + nt * 8];
            mma_f16(acc[nt], fa.x, fa.y, fa.z, fa.w, b0, b1);
        }
    }
    int row0 = wid * 16 + r, row1 = row0 + 8;
#pragma unroll
    for (int nt = 0; nt < 4; ++nt) {
        int kxa = nt * 8 + 2 * c;
        *reinterpret_cast<float2*>(&g_x2r[((size_t)bc * 128 + row0) * 32 + kxa]) =
            make_float2(acc[nt][0], acc[nt][1]);
        *reinterpret_cast<float2*>(&g_x2r[((size_t)bc * 128 + row1) * 32 + kxa]) =
            make_float2(acc[nt][2], acc[nt][3]);
    }
}

// ---------------- K3: per-mode channel mixing (x2 -> y2) -------------------
__global__ __launch_bounds__(256) void k3_mix(const float* __restrict__ spw1,
                                              const float* __restrict__ spw2, int l) {
    __shared__ float2 sX[2 * 64 * 32];                   // [b2][i][kx] 32 KB
    int jj = blockIdx.x >> 2, bp = blockIdx.x & 3;
    int b0 = bp * 2;
    int t = threadIdx.x, kx = t & 31, sub = t >> 5;
    for (int idx = t; idx < 4096; idx += 256) {
        int bi = idx >> 11, rest = idx & 2047;
        int i = rest >> 5, kxl = rest & 31;
        const float* pp = g_x2r + ((size_t)((b0 + bi) * CW + i) * 128 + 2 * jj) * 32;
        sX[idx] = make_float2(pp[kxl], pp[32 + kxl]);
    }
    __syncthreads();
    const float2* wp; int jx;
    if (jj < 32) { wp = (const float2*)spw1; jx = jj; }
    else         { wp = (const float2*)spw2; jx = jj - 32; }
    size_t wbase = (size_t)l * 4194304 + (size_t)jx * 32 + kx;
    float2 a0[8], a1[8];
#pragma unroll
    for (int q = 0; q < 8; ++q) { a0[q] = make_float2(0.f, 0.f); a1[q] = make_float2(0.f, 0.f); }
#pragma unroll 2
    for (int i = 0; i < 64; ++i) {
        float2 x0 = sX[i * 32 + kx];
        float2 x1 = sX[2048 + i * 32 + kx];
        size_t row = wbase + (size_t)(i * 64 + sub * 8) * 1024;
#pragma unroll
        for (int q = 0; q < 8; ++q) {
            float2 c = __ldg(&wp[row + (size_t)q * 1024]);
            a0[q].x = fmaf(x0.x, c.x, a0[q].x); a0[q].x = fmaf(-x0.y, c.y, a0[q].x);
            a0[q].y = fmaf(x0.x, c.y, a0[q].y); a0[q].y = fmaf( x0.y, c.x, a0[q].y);
            a1[q].x = fmaf(x1.x, c.x, a1[q].x); a1[q].x = fmaf(-x1.y, c.y, a1[q].x);
            a1[q].y = fmaf(x1.x, c.y, a1[q].y); a1[q].y = fmaf( x1.y, c.x, a1[q].y);
        }
    }
#pragma unroll
    for (int q = 0; q < 8; ++q) {
        int o = sub * 8 + q;
        g_y2[(((size_t)b0       * CW + o) * MH + jj) * MW + kx] = a0[q];
        g_y2[(((size_t)(b0 + 1) * CW + o) * MH + jj) * MW + kx] = a1[q];
    }
}

// ---------------- K4: inverse H-DFT via fp16 mma ---------------------------
// per (b,o): C[528 h'][32 kx] = A[528][128] x B[128][32]; A const (g_ghfh)
__global__ __launch_bounds__(256) void k4_invh() {
    __shared__ unsigned sBw[64 * 40];
    int bo = blockIdx.x, b = bo >> 6, o = bo & 63;
    int t = threadIdx.x;
    const float2* yp = g_y2 + (size_t)bo * MH * MW;
    for (int idx = t; idx < MH * MW; idx += 256) {
        int j = idx >> 5, kx = idx & 31;
        float2 v = yp[idx];
        sBw[j * 40 + kx] = packh(v.x, v.y);
    }
    __syncthreads();
    int lane = t & 31, wid = t >> 5;
    int c = lane & 3, r = lane >> 2;
    for (int mt = wid; mt < 33; mt += 8) {
        float acc[4][4];
#pragma unroll
        for (int nt = 0; nt < 4; ++nt) {
            acc[nt][0] = 0.f; acc[nt][1] = 0.f; acc[nt][2] = 0.f; acc[nt][3] = 0.f;
        }
#pragma unroll
        for (int kt = 0; kt < 8; ++kt) {
            uint4 fa = __ldg(&g_ghfh[(mt * 8 + kt) * 32 + lane]);
            int bw = (kt * 8 + c) * 40 + r;
#pragma unroll
            for (int nt = 0; nt < 4; ++nt) {
                unsigned b0 = sBw[bw + nt * 8];
                unsigned b1 = sBw[bw + 4 * 40 + nt * 8];
                mma_f16(acc[nt], fa.x, fa.y, fa.z, fa.w, b0, b1);
            }
        }
        int h0a = mt * 16 + r, h0b = h0a + 8;
        int ha = h0a >> 1, pa = h0a & 1;
        int hb2 = h0b >> 1, pb = h0b & 1;
        size_t basea = ((size_t)(b * HP + ha) * 64 + o) * 64 + pa;
        size_t baseb = ((size_t)(b * HP + hb2) * 64 + o) * 64 + pb;
#pragma unroll
        for (int nt = 0; nt < 4; ++nt) {
            int kka = 2 * (nt * 8 + 2 * c);
            g_y1h[basea + kka]     = __float2half_rn(acc[nt][0]);
            g_y1h[basea + kka + 2] = __float2half_rn(acc[nt][1]);
            g_y1h[baseb + kka]     = __float2half_rn(acc[nt][2]);
            g_y1h[baseb + kka + 2] = __float2half_rn(acc[nt][3]);
        }
    }
}

// ---------------- K5: fp16 mma GEMM: conv1x1 + inverse-W(c2r) + bias + gelu
__global__ __launch_bounds__(256, 2)
void k5_combine(int cur, const float* __restrict__ cw,
                const float* __restrict__ cb, int l,
                float* __restrict__ out) {
    extern __shared__ unsigned s_raw_u[];
    unsigned* sAw = s_raw_u;                      // [o][kpair] stride 68 words
    unsigned* sBw = s_raw_u + 64 * 68;            // [kpair][w] stride 264 words (+16 slack)
    int bh = blockIdx.x;
    int b = bh / HP, h = bh - b * HP;
    bool last = (l == NL - 1);
    if (last && h >= H0) return;
    int t = threadIdx.x;
    // stage B (conv half k<64): channel pairs (2kp, 2kp+1), fp16 source
    {
        const __half* hb = g_hh[cur] + ((size_t)b * CW * HP + h) * WP;
        const size_t rstride = (size_t)HP * WP;
        for (int idx = t; idx < 32 * 66; idx += 256) {
            int kp = idx / 66, cq = idx - kp * 66;
            const unsigned* r0 = reinterpret_cast<const unsigned*>(hb + (size_t)(2 * kp) * rstride);
            const unsigned* r1 = reinterpret_cast<const unsigned*>(hb + (size_t)(2 * kp + 1) * rstride);
            uint2 u0 = *reinterpret_cast<const uint2*>(&r0[cq * 2]);
            uint2 u1 = *reinterpret_cast<const uint2*>(&r1[cq * 2]);
            int wb = kp * 264 + cq * 4;
            sBw[wb]     = __byte_perm(u0.x, u1.x, 0x5410);
            sBw[wb + 1] = __byte_perm(u0.x, u1.x, 0x7632);
            sBw[wb + 2] = __byte_perm(u0.y, u1.y, 0x5410);
            sBw[wb + 3] = __byte_perm(u0.y, u1.y, 0x7632);
        }
        if (t < 16) sBw[32 * 264 + t] = 0u;
    }
    // stage A: conv weights (fp32 src) + spectral coeffs (fp16 src, direct copy)
    {
        const float* cwl = cw + (size_t)l * 4096;
        for (int idx = t; idx < 2048; idx += 256) {
            int o = idx >> 5, ip = idx & 31;
            sAw[o * 68 + ip] = packh(cwl[o * 64 + 2 * ip], cwl[o * 64 + 2 * ip + 1]);
        }
        const unsigned* yb = reinterpret_cast<const unsigned*>(
            g_y1h + (size_t)(b * HP + h) * 4096);
        for (int idx = t; idx < 2048; idx += 256) {
            int o = idx >> 5, kp = idx & 31;
            sAw[o * 68 + 32 + kp] = yb[o * 32 + kp];
        }
    }
    __syncthreads();
    int lane = t & 31, wid = t >> 5;
    int mi = wid & 3, nh = wid >> 2;
    int m0 = mi * 16;
    int c = lane & 3, r = lane >> 2;
    int ntBeg = nh * 17;
    float acc[17][4];
#pragma unroll
    for (int j = 0; j < 17; ++j) {
        acc[j][0] = 0.f; acc[j][1] = 0.f; acc[j][2] = 0.f; acc[j][3] = 0.f;
    }
    int aw0 = (m0 + r) * 68 + c;
    int aw1 = aw0 + 8 * 68;
    // conv half (kt 0..3): B from smem
#pragma unroll
    for (int kt = 0; kt < 4; ++kt) {
        unsigned a0 = sAw[aw0 + kt * 8];
        unsigned a1 = sAw[aw1 + kt * 8];
        unsigned a2 = sAw[aw0 + kt * 8 + 4];
        unsigned a3 = sAw[aw1 + kt * 8 + 4];
        int bw = (kt * 8 + c) * 264 + r + ntBeg * 8;
#pragma unroll
        for (int j = 0; j < 17; ++j) {
            unsigned b0 = sBw[bw + j * 8];
            unsigned b1 = sBw[bw + 4 * 264 + j * 8];
            mma_f16(acc[j], a0, a1, a2, a3, b0, b1);
        }
    }
    // spectral half (kt 4..7): B frags pre-swizzled in g_awfh
#pragma unroll
    for (int kt = 4; kt < 8; ++kt) {
        unsigned a0 = sAw[aw0 + kt * 8];
        unsigned a1 = sAw[aw1 + kt * 8];
        unsigned a2 = sAw[aw0 + kt * 8 + 4];
        unsigned a3 = sAw[aw1 + kt * 8 + 4];
        const uint2* bp = &g_awfh[((kt - 4) * 34 + ntBeg) * 32 + lane];
#pragma unroll
        for (int j = 0; j < 17; ++j) {
            uint2 bb = __ldg(&bp[j * 32]);
            mma_f16(acc[j], a0, a1, a2, a3, bb.x, bb.y);
        }
    }
    int o0 = m0 + r, o1 = o0 + 8;
    float bias0 = __ldg(&cb[l * 64 + o0]);
    float bias1 = __ldg(&cb[l * 64 + o1]);
    __half* hn = g_hh[cur ^ 1];
#pragma unroll
    for (int j = 0; j < 17; ++j) {
        if (nh && j == 16) continue;
        int n0 = (ntBeg + j) * 8;
        int wcol = n0 + 2 * c;
        float2 p0 = make_float2(acc[j][0] + bias0, acc[j][1] + bias0);
        float2 p1 = make_float2(acc[j][2] + bias1, acc[j][3] + bias1);
        if (!last) {
            p0.x = gelu_f(p0.x); p0.y = gelu_f(p0.y);
            p1.x = gelu_f(p1.x); p1.y = gelu_f(p1.y);
            *reinterpret_cast<unsigned*>(
                &hn[(((size_t)b * CW + o0) * HP + h) * WP + wcol]) = packh(p0.x, p0.y);
            *reinterpret_cast<unsigned*>(
                &hn[(((size_t)b * CW + o1) * HP + h) * WP + wcol]) = packh(p1.x, p1.y);
        } else if (n0 < W0) {
            *reinterpret_cast<float2*>(
                &out[(((size_t)b * CW + o0) * H0 + h) * W0 + wcol]) = p0;
            *reinterpret_cast<float2*>(
                &out[(((size_t)b * CW + o1) * H0 + h) * W0 + wcol]) = p1;
        }
    }
}

// ---------------- launch ---------------------------------------------------
extern "C" void kernel_launch(void* const* d_in, const int* in_sizes, int n_in,
                              void* d_out, int out_size) {
    const float* x   = (const float*)d_in[0];
    const float* lw1 = (const float*)d_in[1];
    const float* lb1 = (const float*)d_in[2];
    const float* lw2 = (const float*)d_in[3];
    const float* lb2 = (const float*)d_in[4];
    const float* cw  = (const float*)d_in[5];
    const float* cb  = (const float*)d_in[6];
    const float* sp1 = (const float*)d_in[7];
    const float* sp2 = (const float*)d_in[8];
    float* out = (float*)d_out;

    const int SMEM_K1 = (64 * 132 + 8) * 4;                // 33824
    const int SMEM_K2 = 264 * 40 * 4;                      // 42240
    const int SMEM_K5 = (64 * 68 + 32 * 264 + 16) * 4;     // 51264

    cudaFuncSetAttribute(k1_wdft,    cudaFuncAttributeMaxDynamicSharedMemorySize, SMEM_K1);
    cudaFuncSetAttribute(k2_hdft,    cudaFuncAttributeMaxDynamicSharedMemorySize, SMEM_K2);
    cudaFuncSetAttribute(k5_combine, cudaFuncAttributeMaxDynamicSharedMemorySize, SMEM_K5);

    k_init<<<66, 256>>>();
    k_zero_pad<<<BATCH * CW, 256>>>();
    k_lift<<<BATCH * 256, 256>>>(x, lw1, lb1, lw2, lb2);

    for (int l = 0; l < NL; ++l) {
        int cur = l & 1;
        k1_wdft<<<(BATCH * CW * HP) / 64, 256, SMEM_K1>>>(cur);
        k2_hdft<<<BATCH * CW, 256, SMEM_K2>>>();
        k3_mix<<<MH * 4, 256>>>(sp1, sp2, l);
        k4_invh<<<BATCH * CW, 256>>>();
        k5_combine<<<BATCH * HP, 256, SMEM_K5>>>(cur, cw, cb, l, out);
    }
}